// round 1
// baseline (speedup 1.0000x reference)
#include <cuda_runtime.h>
#include <cstdint>

// ---------------------------------------------------------------------------
// ICNN forward + input-gradient, fp32 SIMT baseline.
// out = 0.5 * d(scalar)/dx + 0.5 * x
//
// scalar(x):  u_l = Wq_l x ; v_l = Wl_l x + bl_l ; p_l = u_l^2 + v_l
//             z_0 = lrelu(p_0) ; z_l = lrelu(Wz_{l-1} z_{l-1} + p_l)
//             out = z_9 . wz_out + (x.wq_out)^2 + x.wl_out
//
// grad: backprop masks f_l = (a_l >= 0 ? 1 : 0.2)
//       ga_9 = wz_out * f_9 ; ga_{l} = (ga_{l+1} @ Wz_l) * f_l
//       gx   = sum_l (2 ga_l u_l) @ Wq_l + ga_l @ Wl_l
//              + 2 (x.wq_out) wq_out + wl_out
// ---------------------------------------------------------------------------

#define NEG_SLOPE 0.2f

constexpr int Bsz = 8192;
constexpr int Dd  = 128;
constexpr int Hh  = 512;
constexpr int Ll  = 10;
constexpr int LH  = Ll * Hh;   // 5120

// -------- static device scratch (allocation-free rule) ---------------------
__device__ float         g_U [(size_t)Bsz * LH];   // Wq.x          [B, L*H]
__device__ float         g_P [(size_t)Bsz * LH];   // u^2 + Wl.x+bl [B, L*H]
__device__ float         g_G1[(size_t)Bsz * LH];   // 2*ga*u        [B, L*H]
__device__ float         g_G2[(size_t)Bsz * LH];   // ga            [B, L*H]
__device__ unsigned char g_F [(size_t)Bsz * LH];   // lrelu masks
__device__ float         g_Z0[(size_t)Bsz * Hh];
__device__ float         g_Z1[(size_t)Bsz * Hh];
__device__ float         g_GX[(size_t)Bsz * Dd];
__device__ float         g_S [Bsz];

// -------- epilogue parameter block ------------------------------------------
struct EpiParams {
  float* C;
  const float* U;
  const float* P;
  const float* bl;
  unsigned char* F;
  float* G1;
  float* G2;
  const float* GX;
  const float* S;
  const float* wq;
  const float* wl;
  const float* x;
  int ldc;
  int coff;
};

// EPI codes:
// 0 = plain store C[m*ldc+n] = acc
// 1 = P epilogue:    P = U^2 + (acc + bl[n])                (n global in [0,LH))
// 2 = forward layer: a = acc + P[m,coff+n]; mask; z = lrelu(a)
// 3 = backward layer: ga = acc * f; store Gcur, G2, G1 = 2*ga*U
// 4 = final: out = 0.5*(acc + GX + 2*S[m]*wq[n] + wl[n]) + 0.5*x
template <int BM, int BN, int BK, int TM, int TN, bool BTRANS, int EPI>
__global__ void __launch_bounds__((BM / TM) * (BN / TN))
gemm_k(const float* __restrict__ A, const float* __restrict__ Bm,
       int M, int N, int K, int lda, int ldb, EpiParams ep)
{
  constexpr int THREADS = (BM / TM) * (BN / TN);
  __shared__ float As[BK][BM];
  __shared__ float Bs[BK][BN];

  const int tid = threadIdx.x;
  const int tx  = tid % (BN / TN);
  const int ty  = tid / (BN / TN);
  const int m0  = blockIdx.y * BM;
  const int n0  = blockIdx.x * BN;

  float acc[TM][TN];
#pragma unroll
  for (int i = 0; i < TM; i++)
#pragma unroll
    for (int j = 0; j < TN; j++) acc[i][j] = 0.f;

  constexpr int A_VEC = (BM * BK) / (4 * THREADS);  // float4 loads / thread
  constexpr int B_VEC = (BN * BK) / (4 * THREADS);
  static_assert(A_VEC >= 1 && B_VEC >= 1, "tile/thread mismatch");

  for (int k0 = 0; k0 < K; k0 += BK) {
    // ---- load A tile (row-major [M,K]) into As[k][m] -----------------------
#pragma unroll
    for (int v = 0; v < A_VEC; v++) {
      int idx4 = tid + v * THREADS;
      int row  = idx4 / (BK / 4);
      int cv   = idx4 % (BK / 4);
      float4 t = *reinterpret_cast<const float4*>(
          &A[(size_t)(m0 + row) * lda + k0 + cv * 4]);
      As[cv * 4 + 0][row] = t.x;
      As[cv * 4 + 1][row] = t.y;
      As[cv * 4 + 2][row] = t.z;
      As[cv * 4 + 3][row] = t.w;
    }
    // ---- load B tile -------------------------------------------------------
    if (BTRANS) {
      // B is [N,K] row-major: C = A @ B^T
#pragma unroll
      for (int v = 0; v < B_VEC; v++) {
        int idx4 = tid + v * THREADS;
        int row  = idx4 / (BK / 4);   // n index
        int cv   = idx4 % (BK / 4);
        float4 t = *reinterpret_cast<const float4*>(
            &Bm[(size_t)(n0 + row) * ldb + k0 + cv * 4]);
        Bs[cv * 4 + 0][row] = t.x;
        Bs[cv * 4 + 1][row] = t.y;
        Bs[cv * 4 + 2][row] = t.z;
        Bs[cv * 4 + 3][row] = t.w;
      }
    } else {
      // B is [K,N] row-major
#pragma unroll
      for (int v = 0; v < B_VEC; v++) {
        int idx4 = tid + v * THREADS;
        int kr   = idx4 / (BN / 4);
        int nv   = idx4 % (BN / 4);
        *reinterpret_cast<float4*>(&Bs[kr][nv * 4]) =
            *reinterpret_cast<const float4*>(
                &Bm[(size_t)(k0 + kr) * ldb + n0 + nv * 4]);
      }
    }
    __syncthreads();

    // ---- compute -----------------------------------------------------------
#pragma unroll
    for (int kk = 0; kk < BK; kk++) {
      float a[TM], b[TN];
#pragma unroll
      for (int i = 0; i < TM; i += 4)
        *reinterpret_cast<float4*>(a + i) =
            *reinterpret_cast<const float4*>(&As[kk][ty * TM + i]);
#pragma unroll
      for (int j = 0; j < TN; j += 4)
        *reinterpret_cast<float4*>(b + j) =
            *reinterpret_cast<const float4*>(&Bs[kk][tx * TN + j]);
#pragma unroll
      for (int i = 0; i < TM; i++)
#pragma unroll
        for (int j = 0; j < TN; j++)
          acc[i][j] = fmaf(a[i], b[j], acc[i][j]);
    }
    __syncthreads();
  }

  // ---- epilogue -------------------------------------------------------------
#pragma unroll
  for (int i = 0; i < TM; i++) {
    int m = m0 + ty * TM + i;
#pragma unroll
    for (int j = 0; j < TN; j++) {
      int n   = n0 + tx * TN + j;
      float v = acc[i][j];
      if (EPI == 0) {
        ep.C[(size_t)m * ep.ldc + n] = v;
      } else if (EPI == 1) {
        size_t idx = (size_t)m * LH + n;
        float u    = ep.U[idx];
        ep.C[idx]  = u * u + v + ep.bl[n];
      } else if (EPI == 2) {
        size_t idx = (size_t)m * LH + ep.coff + n;
        float a    = v + ep.P[idx];
        bool pos   = (a >= 0.f);
        ep.F[idx]  = pos ? 1 : 0;
        ep.C[(size_t)m * Hh + n] = pos ? a : NEG_SLOPE * a;
      } else if (EPI == 3) {
        size_t idx = (size_t)m * LH + ep.coff + n;
        float f    = ep.F[idx] ? 1.f : NEG_SLOPE;
        float ga   = v * f;
        ep.C[(size_t)m * Hh + n] = ga;
        ep.G2[idx] = ga;
        ep.G1[idx] = 2.f * ga * ep.U[idx];
      } else {  // EPI == 4
        float tot = v + ep.GX[(size_t)m * Dd + n] + 2.f * ep.S[m] * ep.wq[n] +
                    ep.wl[n];
        ep.C[(size_t)m * Dd + n] =
            0.5f * tot + 0.5f * ep.x[(size_t)m * Dd + n];
      }
    }
  }
}

// -------- elementwise kernels -----------------------------------------------
__global__ void ew_layer0(const float* __restrict__ P, unsigned char* __restrict__ F,
                          float* __restrict__ Z)
{
  int i = blockIdx.x * blockDim.x + threadIdx.x;  // over Bsz*Hh
  int b = i / Hh, h = i % Hh;
  size_t idx = (size_t)b * LH + h;
  float a  = P[idx];
  bool pos = (a >= 0.f);
  F[idx]   = pos ? 1 : 0;
  Z[i]     = pos ? a : NEG_SLOPE * a;
}

__global__ void ew_bwinit(const unsigned char* __restrict__ F,
                          const float* __restrict__ U,
                          const float* __restrict__ wz_out,
                          float* __restrict__ G, float* __restrict__ G1,
                          float* __restrict__ G2)
{
  int i = blockIdx.x * blockDim.x + threadIdx.x;  // over Bsz*Hh
  int b = i / Hh, h = i % Hh;
  size_t idx = (size_t)b * LH + (size_t)(Ll - 1) * Hh + h;
  float f  = F[idx] ? 1.f : NEG_SLOPE;
  float ga = wz_out[h] * f;
  G[i]     = ga;
  G2[idx]  = ga;
  G1[idx]  = 2.f * ga * U[idx];
}

__global__ void ew_dot(const float* __restrict__ x, const float* __restrict__ wq,
                       float* __restrict__ S)
{
  int gid  = blockIdx.x * blockDim.x + threadIdx.x;
  int w    = gid / 32;      // one warp per batch row
  int lane = gid % 32;
  if (w >= Bsz) return;
  float s = 0.f;
  for (int d = lane; d < Dd; d += 32) s += x[(size_t)w * Dd + d] * wq[d];
#pragma unroll
  for (int o = 16; o; o >>= 1) s += __shfl_xor_sync(0xFFFFFFFFu, s, o);
  if (lane == 0) S[w] = s;
}

// -------- launch helper ------------------------------------------------------
template <int BM, int BN, int BK, int TM, int TN, bool BTRANS, int EPI>
static void launch_gemm(const float* A, const float* Bm, int M, int N, int K,
                        int lda, int ldb, const EpiParams& ep)
{
  dim3 grid(N / BN, M / BM);
  dim3 block((BM / TM) * (BN / TN));
  gemm_k<BM, BN, BK, TM, TN, BTRANS, EPI><<<grid, block>>>(A, Bm, M, N, K, lda,
                                                           ldb, ep);
}

extern "C" void kernel_launch(void* const* d_in, const int* in_sizes, int n_in,
                              void* d_out, int out_size)
{
  const float* x      = (const float*)d_in[0];
  const float* Wq     = (const float*)d_in[1];
  const float* Wl     = (const float*)d_in[2];
  const float* bl     = (const float*)d_in[3];
  const float* Wz     = (const float*)d_in[4];
  const float* wz_out = (const float*)d_in[5];
  const float* wq_out = (const float*)d_in[6];
  const float* wl_out = (const float*)d_in[7];
  float* out          = (float*)d_out;

  float *U, *P, *G1, *G2, *Z0, *Z1, *GX, *S;
  unsigned char* F;
  cudaGetSymbolAddress((void**)&U,  g_U);
  cudaGetSymbolAddress((void**)&P,  g_P);
  cudaGetSymbolAddress((void**)&G1, g_G1);
  cudaGetSymbolAddress((void**)&G2, g_G2);
  cudaGetSymbolAddress((void**)&F,  g_F);
  cudaGetSymbolAddress((void**)&Z0, g_Z0);
  cudaGetSymbolAddress((void**)&Z1, g_Z1);
  cudaGetSymbolAddress((void**)&GX, g_GX);
  cudaGetSymbolAddress((void**)&S,  g_S);

  float* zb[2] = {Z0, Z1};

  // 1) U = x @ Wq^T   ([B,D] x [LH,D]^T -> [B,LH])
  {
    EpiParams ep = {};
    ep.C   = U;
    ep.ldc = LH;
    launch_gemm<128, 128, 16, 8, 8, true, 0>(x, Wq, Bsz, LH, Dd, Dd, Dd, ep);
  }
  // 2) P = U^2 + x @ Wl^T + bl
  {
    EpiParams ep = {};
    ep.C  = P;
    ep.U  = U;
    ep.bl = bl;
    launch_gemm<128, 128, 16, 8, 8, true, 1>(x, Wl, Bsz, LH, Dd, Dd, Dd, ep);
  }
  // 3) z0 = lrelu(P[:, 0:H]) + mask
  ew_layer0<<<(Bsz * Hh) / 256, 256>>>(P, F, Z0);

  // 4) forward chain: z_l = lrelu(z_{l-1} @ Wz_{l-1}^T + P_l)
  for (int l = 1; l < Ll; l++) {
    EpiParams ep = {};
    ep.C    = zb[l % 2];
    ep.P    = P;
    ep.F    = F;
    ep.coff = l * Hh;
    launch_gemm<128, 128, 16, 8, 8, true, 2>(
        zb[(l - 1) % 2], Wz + (size_t)(l - 1) * Hh * Hh, Bsz, Hh, Hh, Hh, Hh,
        ep);
  }

  // 5) backward init: ga_9 = wz_out * f_9 ; emit G1/G2 block 9
  ew_bwinit<<<(Bsz * Hh) / 256, 256>>>(F, U, wz_out, zb[0], G1, G2);

  // 6) backward chain: ga_l = (ga_{l+1} @ Wz_l) * f_l ; emit G1/G2 block l
  int cur = 0;
  for (int l = Ll - 2; l >= 0; l--) {
    int nxt      = cur ^ 1;
    EpiParams ep = {};
    ep.C    = zb[nxt];
    ep.F    = F;
    ep.U    = U;
    ep.G1   = G1;
    ep.G2   = G2;
    ep.coff = l * Hh;
    launch_gemm<128, 128, 16, 8, 8, false, 3>(
        zb[cur], Wz + (size_t)l * Hh * Hh, Bsz, Hh, Hh, Hh, Hh, ep);
    cur = nxt;
  }

  // 7) S[b] = x[b] . wq_out
  ew_dot<<<(Bsz * 32) / 256, 256>>>(x, wq_out, S);

  // 8) GX = G1 @ Wq_flat   ([B,LH] x [LH,D])
  {
    EpiParams ep = {};
    ep.C   = GX;
    ep.ldc = Dd;
    launch_gemm<64, 128, 16, 4, 8, false, 0>(G1, Wq, Bsz, Dd, LH, LH, Dd, ep);
  }
  // 9) out = 0.5*(G2 @ Wl_flat + GX + 2*S*wq_out + wl_out) + 0.5*x
  {
    EpiParams ep = {};
    ep.C  = out;
    ep.GX = GX;
    ep.S  = S;
    ep.wq = wq_out;
    ep.wl = wl_out;
    ep.x  = x;
    launch_gemm<64, 128, 16, 4, 8, false, 4>(G2, Wl, Bsz, Dd, LH, LH, Dd, ep);
  }
}

// round 3
// speedup vs baseline: 1.9217x; 1.9217x over previous
#include <cuda_runtime.h>
#include <cuda_bf16.h>
#include <cstdint>

// ===========================================================================
// ICNN forward + input-gradient via mma.sync bf16 (2-way split, 3 products)
// out = 0.5 * d(scalar)/dx + 0.5 * x
// (tcgen05 is 'a'-gated and unavailable under the harness's compute_103 PTX
//  stage; mma.sync.m16n8k16.bf16 is baseline sm_80 PTX and reaches the
//  tensor pipe as HMMA.)
// ===========================================================================

typedef __nv_bfloat16 bf16;

#define NEG_SLOPE 0.2f
constexpr int Bsz = 8192;
constexpr int Dd  = 128;
constexpr int Hh  = 512;
constexpr int Ll  = 10;
constexpr int LH  = Ll * Hh;  // 5120

// ---------------- static device scratch ------------------------------------
__device__ bf16 g_xh[(size_t)Bsz * Dd], g_xl[(size_t)Bsz * Dd];
__device__ bf16 g_Wqh[(size_t)LH * Dd], g_Wql[(size_t)LH * Dd];
__device__ bf16 g_Wlh[(size_t)LH * Dd], g_Wll[(size_t)LH * Dd];
__device__ bf16 g_Wzh[(size_t)(Ll - 1) * Hh * Hh], g_Wzl[(size_t)(Ll - 1) * Hh * Hh];
__device__ bf16 g_WzTh[(size_t)(Ll - 1) * Hh * Hh], g_WzTl[(size_t)(Ll - 1) * Hh * Hh];
__device__ bf16 g_Bch[(size_t)Ll * Dd * 1024], g_Bcl[(size_t)Ll * Dd * 1024];
__device__ float g_U[(size_t)Bsz * LH];
__device__ float g_P[(size_t)Bsz * LH];
__device__ unsigned char g_F[(size_t)Bsz * LH];
__device__ bf16 g_zAh[(size_t)Bsz * Hh], g_zAl[(size_t)Bsz * Hh];
__device__ bf16 g_zBh[(size_t)Bsz * Hh], g_zBl[(size_t)Bsz * Hh];
__device__ bf16 g_Ach[(size_t)Bsz * 1024], g_Acl[(size_t)Bsz * 1024];
__device__ float g_gx[(size_t)Bsz * Dd];
__device__ float g_S[Bsz];

// ---------------- helpers ---------------------------------------------------
__device__ __forceinline__ uint32_t smem_u32(const void* p) {
  uint32_t a;
  asm("{ .reg .u64 t; cvta.to.shared.u64 t, %1; cvt.u32.u64 %0, t; }"
      : "=r"(a) : "l"(p));
  return a;
}
__device__ __forceinline__ void cpa16(uint32_t s, const void* g) {
  asm volatile("cp.async.cg.shared.global [%0], [%1], 16;" ::"r"(s), "l"(g));
}
__device__ __forceinline__ void cpa_commit() {
  asm volatile("cp.async.commit_group;" ::: "memory");
}
__device__ __forceinline__ void cpa_wait0() {
  asm volatile("cp.async.wait_group 0;" ::: "memory");
}
__device__ __forceinline__ void ldsm4(uint32_t addr, uint32_t* r) {
  asm volatile("ldmatrix.sync.aligned.m8n8.x4.shared.b16 {%0,%1,%2,%3}, [%4];"
               : "=r"(r[0]), "=r"(r[1]), "=r"(r[2]), "=r"(r[3]) : "r"(addr));
}
__device__ __forceinline__ void mma16816(float* c, const uint32_t* a,
                                         const uint32_t* b) {
  asm volatile(
      "mma.sync.aligned.m16n8k16.row.col.f32.bf16.bf16.f32 "
      "{%0,%1,%2,%3}, {%4,%5,%6,%7}, {%8,%9}, {%0,%1,%2,%3};"
      : "+f"(c[0]), "+f"(c[1]), "+f"(c[2]), "+f"(c[3])
      : "r"(a[0]), "r"(a[1]), "r"(a[2]), "r"(a[3]), "r"(b[0]), "r"(b[1]));
}
__device__ __forceinline__ void bsplit(float v, bf16& h, bf16& l) {
  h = __float2bfloat16(v);
  l = __float2bfloat16(v - __bfloat162float(h));
}

// ---------------- epilogue params -------------------------------------------
struct EpiP {
  const float* U;
  float* P;
  const float* Pc;
  const float* bl;
  unsigned char* F;
  bf16* zh;
  bf16* zl;
  bf16* ach;
  bf16* acl;
  float* gx;
  float* o32;
  int coff;
};

template <int EPI>
__device__ __forceinline__ void epi_one(int m, int n, float d, const EpiP& ep) {
  if (EPI == 0) {
    ep.o32[(size_t)m * LH + n] = d;
  } else if (EPI == 1) {
    size_t idx = (size_t)m * LH + n;
    float u = ep.U[idx];
    float p = u * u + d + ep.bl[n];
    ep.P[idx] = p;
    if (n < Hh) {
      bool pos = (p >= 0.f);
      ep.F[idx] = pos ? 1 : 0;
      float z = pos ? p : NEG_SLOPE * p;
      bf16 h, l;
      bsplit(z, h, l);
      ep.zh[(size_t)m * Hh + n] = h;
      ep.zl[(size_t)m * Hh + n] = l;
    }
  } else if (EPI == 2) {
    size_t idx = (size_t)m * LH + ep.coff + n;
    float a = d + ep.Pc[idx];
    bool pos = (a >= 0.f);
    ep.F[idx] = pos ? 1 : 0;
    float z = pos ? a : NEG_SLOPE * a;
    bf16 h, l;
    bsplit(z, h, l);
    ep.zh[(size_t)m * Hh + n] = h;
    ep.zl[(size_t)m * Hh + n] = l;
  } else if (EPI == 3) {
    size_t idx = (size_t)m * LH + ep.coff + n;
    float f = ep.F[idx] ? 1.f : NEG_SLOPE;
    float ga = d * f;
    bf16 gh, gl;
    bsplit(ga, gh, gl);
    ep.zh[(size_t)m * Hh + n] = gh;
    ep.zl[(size_t)m * Hh + n] = gl;
    float g1 = 2.f * ga * ep.U[idx];
    bf16 h1, l1;
    bsplit(g1, h1, l1);
    size_t ai = (size_t)m * 1024 + n;
    ep.ach[ai] = h1;
    ep.acl[ai] = l1;
    ep.ach[ai + Hh] = gh;
    ep.acl[ai + Hh] = gl;
  } else {  // EPI == 4: accumulate gx
    atomicAdd(&ep.gx[(size_t)m * Dd + n], d);
  }
}

// ---------------- the GEMM --------------------------------------------------
// C[128, 128] per CTA = (Ah+Al)[M,K] @ (Bh+Bl)[N,K]^T, 3 bf16 products.
// 8 warps, warp tile 32(m) x 64(n). BK = 32, double-buffered via cp.async.
// smem plane: 128 rows x 80B (32 bf16 + 16B pad). Planes: Ah, Al, Bh, Bl.
template <int EPI>
__global__ __launch_bounds__(256) void mma_gemm(
    const bf16* __restrict__ Ah, const bf16* __restrict__ Al,
    const bf16* __restrict__ Bh, const bf16* __restrict__ Bl, int Kc, int lda,
    int ldb, EpiP ep) {
  extern __shared__ char smc[];
  const uint32_t sb = smem_u32(smc);
  const int tid = threadIdx.x, lane = tid & 31, wid = tid >> 5;
  const int m0 = blockIdx.y * 128, n0 = blockIdx.x * 128;
  const int wm = (wid & 3) * 32, wn = (wid >> 2) * 64;
  const int kstart = blockIdx.z * Kc;
  constexpr uint32_t PL = 10240;   // bytes per plane
  constexpr uint32_t STG = 40960;  // bytes per stage (4 planes)

  const int lr = tid >> 1;        // load row 0..127
  const int lc = (tid & 1) * 2;   // chunk base (16B units)

  const bf16* pA0 = Ah + (size_t)(m0 + lr) * lda + lc * 8;
  const bf16* pA1 = Al + (size_t)(m0 + lr) * lda + lc * 8;
  const bf16* pB0 = Bh + (size_t)(n0 + lr) * ldb + lc * 8;
  const bf16* pB1 = Bl + (size_t)(n0 + lr) * ldb + lc * 8;

  auto stage_load = [&](int s, int k0) {
    uint32_t base = sb + (uint32_t)s * STG + (uint32_t)lr * 80 + lc * 16;
    cpa16(base, pA0 + k0);
    cpa16(base + 16, pA0 + k0 + 8);
    cpa16(base + PL, pA1 + k0);
    cpa16(base + PL + 16, pA1 + k0 + 8);
    cpa16(base + 2 * PL, pB0 + k0);
    cpa16(base + 2 * PL + 16, pB0 + k0 + 8);
    cpa16(base + 3 * PL, pB1 + k0);
    cpa16(base + 3 * PL + 16, pB1 + k0 + 8);
    cpa_commit();
  };

  float acc[2][8][4];
#pragma unroll
  for (int i = 0; i < 2; i++)
#pragma unroll
    for (int j = 0; j < 8; j++)
#pragma unroll
      for (int q = 0; q < 4; q++) acc[i][j][q] = 0.f;

  const int nk = Kc / 32;
  stage_load(0, kstart);
  cpa_wait0();
  __syncthreads();

  const int g3 = lane >> 3, r8 = lane & 7;

  for (int kb = 0; kb < nk; ++kb) {
    const int s = kb & 1;
    if (kb + 1 < nk) stage_load(s ^ 1, kstart + (kb + 1) * 32);
    const uint32_t ab = sb + (uint32_t)s * STG;
#pragma unroll
    for (int k16 = 0; k16 < 32; k16 += 16) {
      uint32_t Ahf[2][4], Alf[2][4], Bhf[8][2], Blf[8][2];
#pragma unroll
      for (int mi = 0; mi < 2; mi++) {
        uint32_t row = wm + mi * 16 + (g3 & 1) * 8 + r8;
        uint32_t col = k16 + (g3 >> 1) * 8;
        uint32_t ad = ab + row * 80 + col * 2;
        ldsm4(ad, Ahf[mi]);
        ldsm4(ad + PL, Alf[mi]);
      }
#pragma unroll
      for (int pi = 0; pi < 4; pi++) {
        uint32_t row = wn + (2 * pi + (g3 >> 1)) * 8 + r8;
        uint32_t col = k16 + (g3 & 1) * 8;
        uint32_t ad = ab + 2 * PL + row * 80 + col * 2;
        uint32_t t[4];
        ldsm4(ad, t);
        Bhf[2 * pi][0] = t[0];
        Bhf[2 * pi][1] = t[1];
        Bhf[2 * pi + 1][0] = t[2];
        Bhf[2 * pi + 1][1] = t[3];
        ldsm4(ad + PL, t);
        Blf[2 * pi][0] = t[0];
        Blf[2 * pi][1] = t[1];
        Blf[2 * pi + 1][0] = t[2];
        Blf[2 * pi + 1][1] = t[3];
      }
#pragma unroll
      for (int mi = 0; mi < 2; mi++)
#pragma unroll
        for (int ni = 0; ni < 8; ni++) {
          mma16816(acc[mi][ni], Ahf[mi], Bhf[ni]);
          mma16816(acc[mi][ni], Ahf[mi], Blf[ni]);
          mma16816(acc[mi][ni], Alf[mi], Bhf[ni]);
        }
    }
    cpa_wait0();
    __syncthreads();
  }

  // ---- epilogue ----
  const int g = lane >> 2, t4 = lane & 3;
#pragma unroll
  for (int mi = 0; mi < 2; mi++)
#pragma unroll
    for (int ni = 0; ni < 8; ni++) {
      int m = m0 + wm + mi * 16 + g;
      int n = n0 + wn + ni * 8 + t4 * 2;
      epi_one<EPI>(m, n, acc[mi][ni][0], ep);
      epi_one<EPI>(m, n + 1, acc[mi][ni][1], ep);
      epi_one<EPI>(m + 8, n, acc[mi][ni][2], ep);
      epi_one<EPI>(m + 8, n + 1, acc[mi][ni][3], ep);
    }
}

// ---------------- prep / elementwise ----------------------------------------
__global__ void k_split(const float* __restrict__ in, bf16* __restrict__ h,
                        bf16* __restrict__ l, int n) {
  int i = blockIdx.x * 256 + threadIdx.x;
  if (i < n) {
    bf16 hh, ll;
    bsplit(in[i], hh, ll);
    h[i] = hh;
    l[i] = ll;
  }
}

__global__ void k_wzT(const float* __restrict__ Wz, bf16* __restrict__ h,
                      bf16* __restrict__ l) {
  int i = blockIdx.x * 256 + threadIdx.x;  // (Ll-1)*Hh*Hh
  int lay = i / (Hh * Hh);
  int r = i % (Hh * Hh);
  int o = r / Hh, ii = r % Hh;
  size_t dst = (size_t)lay * Hh * Hh + (size_t)ii * Hh + o;
  bf16 hh, ll;
  bsplit(Wz[i], hh, ll);
  h[dst] = hh;
  l[dst] = ll;
}

__global__ void k_bcat(const float* __restrict__ Wq, const float* __restrict__ Wl,
                       bf16* __restrict__ h, bf16* __restrict__ l) {
  int i = blockIdx.x * 256 + threadIdx.x;  // Ll*Dd*1024
  int lay = i / (Dd * 1024);
  int r = i % (Dd * 1024);
  int d = r / 1024, k = r % 1024;
  float v = (k < Hh) ? Wq[((size_t)lay * Hh + k) * Dd + d]
                     : Wl[((size_t)lay * Hh + (k - Hh)) * Dd + d];
  bf16 hh, ll;
  bsplit(v, hh, ll);
  h[i] = hh;
  l[i] = ll;
}

__global__ void k_dot(const float* __restrict__ x, const float* __restrict__ wq,
                      float* __restrict__ S) {
  int gid = blockIdx.x * 256 + threadIdx.x;
  int w = gid / 32, lane = gid % 32;
  if (w >= Bsz) return;
  float s = 0.f;
  for (int d = lane; d < Dd; d += 32) s += x[(size_t)w * Dd + d] * wq[d];
#pragma unroll
  for (int o = 16; o; o >>= 1) s += __shfl_xor_sync(0xFFFFFFFFu, s, o);
  if (lane == 0) S[w] = s;
}

__global__ void k_bwinit(const unsigned char* __restrict__ F,
                         const float* __restrict__ U,
                         const float* __restrict__ wz_out,
                         bf16* __restrict__ zh, bf16* __restrict__ zl,
                         bf16* __restrict__ ach, bf16* __restrict__ acl) {
  int i = blockIdx.x * 256 + threadIdx.x;  // Bsz*Hh
  int m = i / Hh, h = i % Hh;
  size_t idx = (size_t)m * LH + (size_t)(Ll - 1) * Hh + h;
  float f = F[idx] ? 1.f : NEG_SLOPE;
  float ga = wz_out[h] * f;
  bf16 gh, gl;
  bsplit(ga, gh, gl);
  zh[i] = gh;
  zl[i] = gl;
  float g1 = 2.f * ga * U[idx];
  bf16 h1, l1;
  bsplit(g1, h1, l1);
  size_t ai = (size_t)m * 1024 + h;
  ach[ai] = h1;
  acl[ai] = l1;
  ach[ai + Hh] = gh;
  acl[ai + Hh] = gl;
}

__global__ void k_zero(float* __restrict__ p, int n) {
  int i = blockIdx.x * 256 + threadIdx.x;
  if (i < n) p[i] = 0.f;
}

__global__ void k_final(const float* __restrict__ gx, const float* __restrict__ S,
                        const float* __restrict__ wq, const float* __restrict__ wl,
                        const float* __restrict__ x, float* __restrict__ out) {
  int i = blockIdx.x * 256 + threadIdx.x;  // Bsz*Dd
  int m = i >> 7, n = i & 127;
  out[i] = 0.5f * (gx[i] + 2.f * S[m] * wq[n] + wl[n]) + 0.5f * x[i];
}

// ---------------- host driver ------------------------------------------------
constexpr uint32_t SMEM_SZ = 81920;

extern "C" void kernel_launch(void* const* d_in, const int* in_sizes, int n_in,
                              void* d_out, int out_size) {
  const float* x = (const float*)d_in[0];
  const float* Wq = (const float*)d_in[1];
  const float* Wl = (const float*)d_in[2];
  const float* bl = (const float*)d_in[3];
  const float* Wz = (const float*)d_in[4];
  const float* wz_out = (const float*)d_in[5];
  const float* wq_out = (const float*)d_in[6];
  const float* wl_out = (const float*)d_in[7];
  float* out = (float*)d_out;

  bf16 *xh, *xl, *Wqh, *Wql, *Wlh, *Wll, *Wzh, *Wzl, *WzTh, *WzTl, *Bch, *Bcl;
  bf16 *zAh, *zAl, *zBh, *zBl, *Ach, *Acl;
  float *U, *P, *gx, *S;
  unsigned char* F;
  cudaGetSymbolAddress((void**)&xh, g_xh);
  cudaGetSymbolAddress((void**)&xl, g_xl);
  cudaGetSymbolAddress((void**)&Wqh, g_Wqh);
  cudaGetSymbolAddress((void**)&Wql, g_Wql);
  cudaGetSymbolAddress((void**)&Wlh, g_Wlh);
  cudaGetSymbolAddress((void**)&Wll, g_Wll);
  cudaGetSymbolAddress((void**)&Wzh, g_Wzh);
  cudaGetSymbolAddress((void**)&Wzl, g_Wzl);
  cudaGetSymbolAddress((void**)&WzTh, g_WzTh);
  cudaGetSymbolAddress((void**)&WzTl, g_WzTl);
  cudaGetSymbolAddress((void**)&Bch, g_Bch);
  cudaGetSymbolAddress((void**)&Bcl, g_Bcl);
  cudaGetSymbolAddress((void**)&U, g_U);
  cudaGetSymbolAddress((void**)&P, g_P);
  cudaGetSymbolAddress((void**)&F, g_F);
  cudaGetSymbolAddress((void**)&zAh, g_zAh);
  cudaGetSymbolAddress((void**)&zAl, g_zAl);
  cudaGetSymbolAddress((void**)&zBh, g_zBh);
  cudaGetSymbolAddress((void**)&zBl, g_zBl);
  cudaGetSymbolAddress((void**)&Ach, g_Ach);
  cudaGetSymbolAddress((void**)&Acl, g_Acl);
  cudaGetSymbolAddress((void**)&gx, g_gx);
  cudaGetSymbolAddress((void**)&S, g_S);

  cudaFuncSetAttribute(mma_gemm<0>, cudaFuncAttributeMaxDynamicSharedMemorySize, SMEM_SZ);
  cudaFuncSetAttribute(mma_gemm<1>, cudaFuncAttributeMaxDynamicSharedMemorySize, SMEM_SZ);
  cudaFuncSetAttribute(mma_gemm<2>, cudaFuncAttributeMaxDynamicSharedMemorySize, SMEM_SZ);
  cudaFuncSetAttribute(mma_gemm<3>, cudaFuncAttributeMaxDynamicSharedMemorySize, SMEM_SZ);
  cudaFuncSetAttribute(mma_gemm<4>, cudaFuncAttributeMaxDynamicSharedMemorySize, SMEM_SZ);

  // ---- prep ----
  k_split<<<(Bsz * Dd + 255) / 256, 256>>>(x, xh, xl, Bsz * Dd);
  k_split<<<(LH * Dd + 255) / 256, 256>>>(Wq, Wqh, Wql, LH * Dd);
  k_split<<<(LH * Dd + 255) / 256, 256>>>(Wl, Wlh, Wll, LH * Dd);
  k_split<<<((Ll - 1) * Hh * Hh + 255) / 256, 256>>>(Wz, Wzh, Wzl,
                                                     (Ll - 1) * Hh * Hh);
  k_wzT<<<((Ll - 1) * Hh * Hh + 255) / 256, 256>>>(Wz, WzTh, WzTl);
  k_bcat<<<(Ll * Dd * 1024 + 255) / 256, 256>>>(Wq, Wl, Bch, Bcl);
  k_dot<<<(Bsz * 32 + 255) / 256, 256>>>(x, wq_out, S);
  k_zero<<<(Bsz * Dd + 255) / 256, 256>>>(gx, Bsz * Dd);

  // ---- head: U = x @ Wq^T ----
  {
    EpiP ep = {};
    ep.o32 = U;
    mma_gemm<0><<<dim3(LH / 128, Bsz / 128, 1), 256, SMEM_SZ>>>(
        xh, xl, Wqh, Wql, Dd, Dd, Dd, ep);
  }
  // ---- head: P = U^2 + x @ Wl^T + bl (+ z0, F0) ----
  {
    EpiP ep = {};
    ep.U = U;
    ep.P = P;
    ep.bl = bl;
    ep.F = F;
    ep.zh = zAh;
    ep.zl = zAl;
    mma_gemm<1><<<dim3(LH / 128, Bsz / 128, 1), 256, SMEM_SZ>>>(
        xh, xl, Wlh, Wll, Dd, Dd, Dd, ep);
  }
  // ---- forward chain ----
  bf16* zh2[2] = {zAh, zBh};
  bf16* zl2[2] = {zAl, zBl};
  for (int l = 1; l < Ll; ++l) {
    EpiP ep = {};
    ep.Pc = P;
    ep.F = F;
    ep.coff = l * Hh;
    ep.zh = zh2[l & 1];
    ep.zl = zl2[l & 1];
    mma_gemm<2><<<dim3(Hh / 128, Bsz / 128, 1), 256, SMEM_SZ>>>(
        zh2[(l - 1) & 1], zl2[(l - 1) & 1], Wzh + (size_t)(l - 1) * Hh * Hh,
        Wzl + (size_t)(l - 1) * Hh * Hh, Hh, Hh, Hh, ep);
  }
  // ---- backward init (layer 9): ga9 -> z buffer 0 + Acat ----
  k_bwinit<<<(Bsz * Hh + 255) / 256, 256>>>(F, U, wz_out, zh2[0], zl2[0], Ach,
                                            Acl);
  // ---- tail l=9 ----
  {
    EpiP ep = {};
    ep.gx = gx;
    mma_gemm<4><<<dim3(1, Bsz / 128, 2), 256, SMEM_SZ>>>(
        Ach, Acl, Bch + (size_t)(Ll - 1) * Dd * 1024,
        Bcl + (size_t)(Ll - 1) * Dd * 1024, 512, 1024, 1024, ep);
  }
  // ---- backward chain + per-layer tail ----
  int cur = 0;
  for (int l = Ll - 2; l >= 0; --l) {
    {
      EpiP ep = {};
      ep.F = F;
      ep.U = U;
      ep.coff = l * Hh;
      ep.zh = zh2[cur ^ 1];
      ep.zl = zl2[cur ^ 1];
      ep.ach = Ach;
      ep.acl = Acl;
      mma_gemm<3><<<dim3(Hh / 128, Bsz / 128, 1), 256, SMEM_SZ>>>(
          zh2[cur], zl2[cur], WzTh + (size_t)l * Hh * Hh,
          WzTl + (size_t)l * Hh * Hh, Hh, Hh, Hh, ep);
      cur ^= 1;
    }
    EpiP ep = {};
    ep.gx = gx;
    mma_gemm<4><<<dim3(1, Bsz / 128, 2), 256, SMEM_SZ>>>(
        Ach, Acl, Bch + (size_t)l * Dd * 1024, Bcl + (size_t)l * Dd * 1024, 512,
        1024, 1024, ep);
  }
  // ---- final combine ----
  k_final<<<(Bsz * Dd + 255) / 256, 256>>>(gx, S, wq_out, wl_out, x, out);
}

// round 4
// speedup vs baseline: 2.0305x; 1.0566x over previous
#include <cuda_runtime.h>
#include <cuda_bf16.h>
#include <cstdint>

// ===========================================================================
// ICNN forward + input-gradient via mma.sync bf16 (2-way split, 3 products).
// Round 4: fused dual-output head GEMM; multi-stream graph with tails
// overlapped against the backward chain; merged prep kernels.
// ===========================================================================

typedef __nv_bfloat16 bf16;

#define NEG_SLOPE 0.2f
constexpr int Bsz = 8192;
constexpr int Dd  = 128;
constexpr int Hh  = 512;
constexpr int Ll  = 10;
constexpr int LH  = Ll * Hh;  // 5120

// ---------------- static device scratch ------------------------------------
__device__ bf16 g_xh[(size_t)Bsz * Dd], g_xl[(size_t)Bsz * Dd];
__device__ bf16 g_Wqh[(size_t)LH * Dd], g_Wql[(size_t)LH * Dd];
__device__ bf16 g_Wlh[(size_t)LH * Dd], g_Wll[(size_t)LH * Dd];
__device__ bf16 g_Wzh[(size_t)(Ll - 1) * Hh * Hh], g_Wzl[(size_t)(Ll - 1) * Hh * Hh];
__device__ bf16 g_WzTh[(size_t)(Ll - 1) * Hh * Hh], g_WzTl[(size_t)(Ll - 1) * Hh * Hh];
__device__ bf16 g_Bch[(size_t)Ll * Dd * 1024], g_Bcl[(size_t)Ll * Dd * 1024];
__device__ float g_U[(size_t)Bsz * LH];
__device__ float g_P[(size_t)Bsz * LH];
__device__ unsigned char g_F[(size_t)Bsz * LH];
__device__ bf16 g_zAh[(size_t)Bsz * Hh], g_zAl[(size_t)Bsz * Hh];
__device__ bf16 g_zBh[(size_t)Bsz * Hh], g_zBl[(size_t)Bsz * Hh];
__device__ bf16 g_Ach0[(size_t)Bsz * 1024], g_Acl0[(size_t)Bsz * 1024];
__device__ bf16 g_Ach1[(size_t)Bsz * 1024], g_Acl1[(size_t)Bsz * 1024];
__device__ float g_gx[(size_t)Bsz * Dd];
__device__ float g_S[Bsz];

// ---------------- helpers ---------------------------------------------------
__device__ __forceinline__ uint32_t smem_u32(const void* p) {
  uint32_t a;
  asm("{ .reg .u64 t; cvta.to.shared.u64 t, %1; cvt.u32.u64 %0, t; }"
      : "=r"(a) : "l"(p));
  return a;
}
__device__ __forceinline__ void cpa16(uint32_t s, const void* g) {
  asm volatile("cp.async.cg.shared.global [%0], [%1], 16;" ::"r"(s), "l"(g));
}
__device__ __forceinline__ void cpa_commit() {
  asm volatile("cp.async.commit_group;" ::: "memory");
}
__device__ __forceinline__ void cpa_wait0() {
  asm volatile("cp.async.wait_group 0;" ::: "memory");
}
__device__ __forceinline__ void ldsm4(uint32_t addr, uint32_t* r) {
  asm volatile("ldmatrix.sync.aligned.m8n8.x4.shared.b16 {%0,%1,%2,%3}, [%4];"
               : "=r"(r[0]), "=r"(r[1]), "=r"(r[2]), "=r"(r[3]) : "r"(addr));
}
__device__ __forceinline__ void mma16816(float* c, const uint32_t* a,
                                         const uint32_t* b) {
  asm volatile(
      "mma.sync.aligned.m16n8k16.row.col.f32.bf16.bf16.f32 "
      "{%0,%1,%2,%3}, {%4,%5,%6,%7}, {%8,%9}, {%0,%1,%2,%3};"
      : "+f"(c[0]), "+f"(c[1]), "+f"(c[2]), "+f"(c[3])
      : "r"(a[0]), "r"(a[1]), "r"(a[2]), "r"(a[3]), "r"(b[0]), "r"(b[1]));
}
__device__ __forceinline__ void bsplit(float v, bf16& h, bf16& l) {
  h = __float2bfloat16(v);
  l = __float2bfloat16(v - __bfloat162float(h));
}

// ---------------- epilogue params -------------------------------------------
struct EpiP {
  const float* U;
  const float* Pc;
  unsigned char* F;
  bf16* zh;
  bf16* zl;
  bf16* ach;
  bf16* acl;
  float* gx;
  int coff;
};

// EPI: 2=fwd layer; 3=bwd layer; 4=gx accum
template <int EPI>
__device__ __forceinline__ void epi_one(int m, int n, float d, const EpiP& ep) {
  if (EPI == 2) {
    size_t idx = (size_t)m * LH + ep.coff + n;
    float a = d + ep.Pc[idx];
    bool pos = (a >= 0.f);
    ep.F[idx] = pos ? 1 : 0;
    float z = pos ? a : NEG_SLOPE * a;
    bf16 h, l;
    bsplit(z, h, l);
    ep.zh[(size_t)m * Hh + n] = h;
    ep.zl[(size_t)m * Hh + n] = l;
  } else if (EPI == 3) {
    size_t idx = (size_t)m * LH + ep.coff + n;
    float f = ep.F[idx] ? 1.f : NEG_SLOPE;
    float ga = d * f;
    bf16 gh, gl;
    bsplit(ga, gh, gl);
    ep.zh[(size_t)m * Hh + n] = gh;
    ep.zl[(size_t)m * Hh + n] = gl;
    float g1 = 2.f * ga * ep.U[idx];
    bf16 h1, l1;
    bsplit(g1, h1, l1);
    size_t ai = (size_t)m * 1024 + n;
    ep.ach[ai] = h1;
    ep.acl[ai] = l1;
    ep.ach[ai + Hh] = gh;
    ep.acl[ai + Hh] = gl;
  } else {  // EPI == 4
    atomicAdd(&ep.gx[(size_t)m * Dd + n], d);
  }
}

// ---------------- chain / tail GEMM -----------------------------------------
// C[128,128]/CTA = (Ah+Al)[M,K] @ (Bh+Bl)[N,K]^T, 3 bf16 products.
// 8 warps, warp tile 32x64. BK=32 double-buffered cp.async.
template <int EPI>
__global__ __launch_bounds__(256) void mma_gemm(
    const bf16* __restrict__ Ah, const bf16* __restrict__ Al,
    const bf16* __restrict__ Bh, const bf16* __restrict__ Bl, int Kc, int lda,
    int ldb, EpiP ep) {
  extern __shared__ char smc[];
  const uint32_t sb = smem_u32(smc);
  const int tid = threadIdx.x, lane = tid & 31, wid = tid >> 5;
  const int m0 = blockIdx.y * 128, n0 = blockIdx.x * 128;
  const int wm = (wid & 3) * 32, wn = (wid >> 2) * 64;
  const int kstart = blockIdx.z * Kc;
  constexpr uint32_t PL = 10240;
  constexpr uint32_t STG = 40960;

  const int lr = tid >> 1;
  const int lc = (tid & 1) * 2;

  const bf16* pA0 = Ah + (size_t)(m0 + lr) * lda + lc * 8;
  const bf16* pA1 = Al + (size_t)(m0 + lr) * lda + lc * 8;
  const bf16* pB0 = Bh + (size_t)(n0 + lr) * ldb + lc * 8;
  const bf16* pB1 = Bl + (size_t)(n0 + lr) * ldb + lc * 8;

  auto stage_load = [&](int s, int k0) {
    uint32_t base = sb + (uint32_t)s * STG + (uint32_t)lr * 80 + lc * 16;
    cpa16(base, pA0 + k0);
    cpa16(base + 16, pA0 + k0 + 8);
    cpa16(base + PL, pA1 + k0);
    cpa16(base + PL + 16, pA1 + k0 + 8);
    cpa16(base + 2 * PL, pB0 + k0);
    cpa16(base + 2 * PL + 16, pB0 + k0 + 8);
    cpa16(base + 3 * PL, pB1 + k0);
    cpa16(base + 3 * PL + 16, pB1 + k0 + 8);
    cpa_commit();
  };

  float acc[2][8][4];
#pragma unroll
  for (int i = 0; i < 2; i++)
#pragma unroll
    for (int j = 0; j < 8; j++)
#pragma unroll
      for (int q = 0; q < 4; q++) acc[i][j][q] = 0.f;

  const int nk = Kc / 32;
  stage_load(0, kstart);
  cpa_wait0();
  __syncthreads();

  const int g3 = lane >> 3, r8 = lane & 7;

  for (int kb = 0; kb < nk; ++kb) {
    const int s = kb & 1;
    if (kb + 1 < nk) stage_load(s ^ 1, kstart + (kb + 1) * 32);
    const uint32_t ab = sb + (uint32_t)s * STG;
#pragma unroll
    for (int k16 = 0; k16 < 32; k16 += 16) {
      uint32_t Ahf[2][4], Alf[2][4], Bhf[8][2], Blf[8][2];
#pragma unroll
      for (int mi = 0; mi < 2; mi++) {
        uint32_t row = wm + mi * 16 + (g3 & 1) * 8 + r8;
        uint32_t col = k16 + (g3 >> 1) * 8;
        uint32_t ad = ab + row * 80 + col * 2;
        ldsm4(ad, Ahf[mi]);
        ldsm4(ad + PL, Alf[mi]);
      }
#pragma unroll
      for (int pi = 0; pi < 4; pi++) {
        uint32_t row = wn + (2 * pi + (g3 >> 1)) * 8 + r8;
        uint32_t col = k16 + (g3 & 1) * 8;
        uint32_t ad = ab + 2 * PL + row * 80 + col * 2;
        uint32_t t[4];
        ldsm4(ad, t);
        Bhf[2 * pi][0] = t[0];
        Bhf[2 * pi][1] = t[1];
        Bhf[2 * pi + 1][0] = t[2];
        Bhf[2 * pi + 1][1] = t[3];
        ldsm4(ad + PL, t);
        Blf[2 * pi][0] = t[0];
        Blf[2 * pi][1] = t[1];
        Blf[2 * pi + 1][0] = t[2];
        Blf[2 * pi + 1][1] = t[3];
      }
#pragma unroll
      for (int mi = 0; mi < 2; mi++)
#pragma unroll
        for (int ni = 0; ni < 8; ni++) {
          mma16816(acc[mi][ni], Ahf[mi], Bhf[ni]);
          mma16816(acc[mi][ni], Ahf[mi], Blf[ni]);
          mma16816(acc[mi][ni], Alf[mi], Bhf[ni]);
        }
    }
    cpa_wait0();
    __syncthreads();
  }

  const int g = lane >> 2, t4 = lane & 3;
#pragma unroll
  for (int mi = 0; mi < 2; mi++)
#pragma unroll
    for (int ni = 0; ni < 8; ni++) {
      int m = m0 + wm + mi * 16 + g;
      int n = n0 + wn + ni * 8 + t4 * 2;
      epi_one<EPI>(m, n, acc[mi][ni][0], ep);
      epi_one<EPI>(m, n + 1, acc[mi][ni][1], ep);
      epi_one<EPI>(m + 8, n, acc[mi][ni][2], ep);
      epi_one<EPI>(m + 8, n + 1, acc[mi][ni][3], ep);
    }
}

// ---------------- fused head GEMM -------------------------------------------
// One pass: U = x@Wq^T (store), P = U^2 + x@Wl^T + bl (store), z0/F for n<Hh.
// CTA tile 128(m) x 64(n), dual accumulators, 8 warps warp-tile 32x32.
__global__ __launch_bounds__(256) void head_gemm(
    const bf16* __restrict__ Axh, const bf16* __restrict__ Axl,
    const bf16* __restrict__ Wqh, const bf16* __restrict__ Wql,
    const bf16* __restrict__ Wlh, const bf16* __restrict__ Wll,
    const float* __restrict__ blv, float* __restrict__ U,
    float* __restrict__ P, unsigned char* __restrict__ F,
    bf16* __restrict__ zh, bf16* __restrict__ zl) {
  extern __shared__ char smc[];
  const uint32_t sb = smem_u32(smc);
  const int tid = threadIdx.x, lane = tid & 31, wid = tid >> 5;
  const int m0 = blockIdx.y * 128, n0 = blockIdx.x * 64;
  const int wm = (wid & 3) * 32, wn = (wid >> 2) * 32;
  constexpr uint32_t PA = 10240;  // 128 rows x 80B
  constexpr uint32_t PB = 5120;   // 64 rows x 80B
  constexpr uint32_t STG = 2 * PA + 4 * PB;  // 40960

  // A loader: 2 threads/row
  const int lr = tid >> 1, lc = (tid & 1) * 2;
  const bf16* pA0 = Axh + (size_t)(m0 + lr) * Dd + lc * 8;
  const bf16* pA1 = Axl + (size_t)(m0 + lr) * Dd + lc * 8;
  // B loader: 128 threads per weight; 2 threads/row
  const int br = (tid & 127) >> 1, bcp = (tid & 1) * 2;
  const int bw = tid >> 7;  // 0 -> Wq, 1 -> Wl
  const bf16* pB0 = (bw ? Wlh : Wqh) + (size_t)(n0 + br) * Dd + bcp * 8;
  const bf16* pB1 = (bw ? Wll : Wql) + (size_t)(n0 + br) * Dd + bcp * 8;
  const uint32_t bOff = 2 * PA + (uint32_t)bw * 2 * PB + (uint32_t)br * 80 + bcp * 16;

  auto stage_load = [&](int s, int k0) {
    uint32_t base = sb + (uint32_t)s * STG;
    uint32_t aA = base + (uint32_t)lr * 80 + lc * 16;
    cpa16(aA, pA0 + k0);
    cpa16(aA + 16, pA0 + k0 + 8);
    cpa16(aA + PA, pA1 + k0);
    cpa16(aA + PA + 16, pA1 + k0 + 8);
    uint32_t aB = base + bOff;
    cpa16(aB, pB0 + k0);
    cpa16(aB + 16, pB0 + k0 + 8);
    cpa16(aB + PB, pB1 + k0);
    cpa16(aB + PB + 16, pB1 + k0 + 8);
    cpa_commit();
  };

  float accq[2][4][4], accl[2][4][4];
#pragma unroll
  for (int i = 0; i < 2; i++)
#pragma unroll
    for (int j = 0; j < 4; j++)
#pragma unroll
      for (int q = 0; q < 4; q++) accq[i][j][q] = accl[i][j][q] = 0.f;

  constexpr int nk = Dd / 32;  // 4
  stage_load(0, 0);
  cpa_wait0();
  __syncthreads();

  const int g3 = lane >> 3, r8 = lane & 7;

  for (int kb = 0; kb < nk; ++kb) {
    const int s = kb & 1;
    if (kb + 1 < nk) stage_load(s ^ 1, (kb + 1) * 32);
    const uint32_t ab = sb + (uint32_t)s * STG;
#pragma unroll
    for (int k16 = 0; k16 < 32; k16 += 16) {
      uint32_t Ahf[2][4], Alf[2][4];
      uint32_t Bqh_[4][2], Bql_[4][2], Blh_[4][2], Bll_[4][2];
#pragma unroll
      for (int mi = 0; mi < 2; mi++) {
        uint32_t row = wm + mi * 16 + (g3 & 1) * 8 + r8;
        uint32_t col = k16 + (g3 >> 1) * 8;
        uint32_t ad = ab + row * 80 + col * 2;
        ldsm4(ad, Ahf[mi]);
        ldsm4(ad + PA, Alf[mi]);
      }
#pragma unroll
      for (int pi = 0; pi < 2; pi++) {
        uint32_t row = wn + (2 * pi + (g3 >> 1)) * 8 + r8;
        uint32_t col = k16 + (g3 & 1) * 8;
        uint32_t adq = ab + 2 * PA + row * 80 + col * 2;
        uint32_t t[4];
        ldsm4(adq, t);
        Bqh_[2 * pi][0] = t[0]; Bqh_[2 * pi][1] = t[1];
        Bqh_[2 * pi + 1][0] = t[2]; Bqh_[2 * pi + 1][1] = t[3];
        ldsm4(adq + PB, t);
        Bql_[2 * pi][0] = t[0]; Bql_[2 * pi][1] = t[1];
        Bql_[2 * pi + 1][0] = t[2]; Bql_[2 * pi + 1][1] = t[3];
        ldsm4(adq + 2 * PB, t);
        Blh_[2 * pi][0] = t[0]; Blh_[2 * pi][1] = t[1];
        Blh_[2 * pi + 1][0] = t[2]; Blh_[2 * pi + 1][1] = t[3];
        ldsm4(adq + 3 * PB, t);
        Bll_[2 * pi][0] = t[0]; Bll_[2 * pi][1] = t[1];
        Bll_[2 * pi + 1][0] = t[2]; Bll_[2 * pi + 1][1] = t[3];
      }
#pragma unroll
      for (int mi = 0; mi < 2; mi++)
#pragma unroll
        for (int ni = 0; ni < 4; ni++) {
          mma16816(accq[mi][ni], Ahf[mi], Bqh_[ni]);
          mma16816(accq[mi][ni], Ahf[mi], Bql_[ni]);
          mma16816(accq[mi][ni], Alf[mi], Bqh_[ni]);
          mma16816(accl[mi][ni], Ahf[mi], Blh_[ni]);
          mma16816(accl[mi][ni], Ahf[mi], Bll_[ni]);
          mma16816(accl[mi][ni], Alf[mi], Blh_[ni]);
        }
    }
    cpa_wait0();
    __syncthreads();
  }

  // epilogue
  const int g = lane >> 2, t4 = lane & 3;
#pragma unroll
  for (int mi = 0; mi < 2; mi++)
#pragma unroll
    for (int ni = 0; ni < 4; ni++) {
#pragma unroll
      for (int q = 0; q < 4; q++) {
        int m = m0 + wm + mi * 16 + g + (q >> 1) * 8;
        int n = n0 + wn + ni * 8 + t4 * 2 + (q & 1);
        float u = accq[mi][ni][q];
        float v = accl[mi][ni][q];
        size_t idx = (size_t)m * LH + n;
        U[idx] = u;
        float p = u * u + v + blv[n];
        P[idx] = p;
        if (n < Hh) {
          bool pos = (p >= 0.f);
          F[idx] = pos ? 1 : 0;
          float z = pos ? p : NEG_SLOPE * p;
          bf16 h, l;
          bsplit(z, h, l);
          zh[(size_t)m * Hh + n] = h;
          zl[(size_t)m * Hh + n] = l;
        }
      }
    }
}

// ---------------- prep / elementwise ----------------------------------------
__global__ void k_split3(const float* __restrict__ x, const float* __restrict__ Wq,
                         const float* __restrict__ Wl, bf16* __restrict__ xh,
                         bf16* __restrict__ xl, bf16* __restrict__ qh,
                         bf16* __restrict__ ql, bf16* __restrict__ lh,
                         bf16* __restrict__ ll) {
  int i = blockIdx.x * 256 + threadIdx.x;
  const int n1 = Bsz * Dd, n2 = LH * Dd;
  bf16 h, l;
  if (i < n1) {
    bsplit(x[i], h, l);
    xh[i] = h; xl[i] = l;
  } else if (i < n1 + n2) {
    int j = i - n1;
    bsplit(Wq[j], h, l);
    qh[j] = h; ql[j] = l;
  } else if (i < n1 + 2 * n2) {
    int j = i - n1 - n2;
    bsplit(Wl[j], h, l);
    lh[j] = h; ll[j] = l;
  }
}

__global__ void k_split(const float* __restrict__ in, bf16* __restrict__ h,
                        bf16* __restrict__ l, int n) {
  int i = blockIdx.x * 256 + threadIdx.x;
  if (i < n) {
    bf16 hh, ll;
    bsplit(in[i], hh, ll);
    h[i] = hh;
    l[i] = ll;
  }
}

__global__ void k_wzT(const float* __restrict__ Wz, bf16* __restrict__ h,
                      bf16* __restrict__ l) {
  int i = blockIdx.x * 256 + threadIdx.x;
  int lay = i / (Hh * Hh);
  int r = i % (Hh * Hh);
  int o = r / Hh, ii = r % Hh;
  size_t dst = (size_t)lay * Hh * Hh + (size_t)ii * Hh + o;
  bf16 hh, ll;
  bsplit(Wz[i], hh, ll);
  h[dst] = hh;
  l[dst] = ll;
}

__global__ void k_bcat(const float* __restrict__ Wq, const float* __restrict__ Wl,
                       bf16* __restrict__ h, bf16* __restrict__ l) {
  int i = blockIdx.x * 256 + threadIdx.x;
  int lay = i / (Dd * 1024);
  int r = i % (Dd * 1024);
  int d = r / 1024, k = r % 1024;
  float v = (k < Hh) ? Wq[((size_t)lay * Hh + k) * Dd + d]
                     : Wl[((size_t)lay * Hh + (k - Hh)) * Dd + d];
  bf16 hh, ll;
  bsplit(v, hh, ll);
  h[i] = hh;
  l[i] = ll;
}

__global__ void k_dotzero(const float* __restrict__ x, const float* __restrict__ wq,
                          float* __restrict__ S, float* __restrict__ gx) {
  int gid = blockIdx.x * 256 + threadIdx.x;
  // zero gx (Bsz*Dd = 1,048,576 elems; grid covers it)
  if (gid < Bsz * Dd) gx[gid] = 0.f;
  int w = gid / 32, lane = gid % 32;
  if (w < Bsz) {
    float s = 0.f;
    for (int d = lane; d < Dd; d += 32) s += x[(size_t)w * Dd + d] * wq[d];
#pragma unroll
    for (int o = 16; o; o >>= 1) s += __shfl_xor_sync(0xFFFFFFFFu, s, o);
    if (lane == 0) S[w] = s;
  }
}

__global__ void k_bwinit(const unsigned char* __restrict__ F,
                         const float* __restrict__ U,
                         const float* __restrict__ wz_out,
                         bf16* __restrict__ zh, bf16* __restrict__ zl,
                         bf16* __restrict__ ach, bf16* __restrict__ acl) {
  int i = blockIdx.x * 256 + threadIdx.x;
  int m = i / Hh, h = i % Hh;
  size_t idx = (size_t)m * LH + (size_t)(Ll - 1) * Hh + h;
  float f = F[idx] ? 1.f : NEG_SLOPE;
  float ga = wz_out[h] * f;
  bf16 gh, gl;
  bsplit(ga, gh, gl);
  zh[i] = gh;
  zl[i] = gl;
  float g1 = 2.f * ga * U[idx];
  bf16 h1, l1;
  bsplit(g1, h1, l1);
  size_t ai = (size_t)m * 1024 + h;
  ach[ai] = h1;
  acl[ai] = l1;
  ach[ai + Hh] = gh;
  acl[ai + Hh] = gl;
}

__global__ void k_final(const float* __restrict__ gx, const float* __restrict__ S,
                        const float* __restrict__ wq, const float* __restrict__ wl,
                        const float* __restrict__ x, float* __restrict__ out) {
  int i = blockIdx.x * 256 + threadIdx.x;
  int m = i >> 7, n = i & 127;
  out[i] = 0.5f * (gx[i] + 2.f * S[m] * wq[n] + wl[n]) + 0.5f * x[i];
}

// ---------------- host driver ------------------------------------------------
constexpr uint32_t SMEM_SZ = 81920;

extern "C" void kernel_launch(void* const* d_in, const int* in_sizes, int n_in,
                              void* d_out, int out_size) {
  const float* x = (const float*)d_in[0];
  const float* Wq = (const float*)d_in[1];
  const float* Wl = (const float*)d_in[2];
  const float* bl = (const float*)d_in[3];
  const float* Wz = (const float*)d_in[4];
  const float* wz_out = (const float*)d_in[5];
  const float* wq_out = (const float*)d_in[6];
  const float* wl_out = (const float*)d_in[7];
  float* out = (float*)d_out;

  bf16 *xh, *xl, *Wqh, *Wql, *Wlh, *Wll, *Wzh, *Wzl, *WzTh, *WzTl, *Bch, *Bcl;
  bf16 *zAh, *zAl, *zBh, *zBl;
  bf16 *Ach[2], *Acl[2];
  float *U, *P, *gx, *S;
  unsigned char* F;
  cudaGetSymbolAddress((void**)&xh, g_xh);
  cudaGetSymbolAddress((void**)&xl, g_xl);
  cudaGetSymbolAddress((void**)&Wqh, g_Wqh);
  cudaGetSymbolAddress((void**)&Wql, g_Wql);
  cudaGetSymbolAddress((void**)&Wlh, g_Wlh);
  cudaGetSymbolAddress((void**)&Wll, g_Wll);
  cudaGetSymbolAddress((void**)&Wzh, g_Wzh);
  cudaGetSymbolAddress((void**)&Wzl, g_Wzl);
  cudaGetSymbolAddress((void**)&WzTh, g_WzTh);
  cudaGetSymbolAddress((void**)&WzTl, g_WzTl);
  cudaGetSymbolAddress((void**)&Bch, g_Bch);
  cudaGetSymbolAddress((void**)&Bcl, g_Bcl);
  cudaGetSymbolAddress((void**)&U, g_U);
  cudaGetSymbolAddress((void**)&P, g_P);
  cudaGetSymbolAddress((void**)&F, g_F);
  cudaGetSymbolAddress((void**)&zAh, g_zAh);
  cudaGetSymbolAddress((void**)&zAl, g_zAl);
  cudaGetSymbolAddress((void**)&zBh, g_zBh);
  cudaGetSymbolAddress((void**)&zBl, g_zBl);
  cudaGetSymbolAddress((void**)&Ach[0], g_Ach0);
  cudaGetSymbolAddress((void**)&Acl[0], g_Acl0);
  cudaGetSymbolAddress((void**)&Ach[1], g_Ach1);
  cudaGetSymbolAddress((void**)&Acl[1], g_Acl1);
  cudaGetSymbolAddress((void**)&gx, g_gx);
  cudaGetSymbolAddress((void**)&S, g_S);

  static bool s_init = false;
  static cudaStream_t st1, st2;
  static cudaEvent_t evStart, evWz, evWzT, evBw[10], evTail[10];
  if (!s_init) {
    cudaStreamCreateWithFlags(&st1, cudaStreamNonBlocking);
    cudaStreamCreateWithFlags(&st2, cudaStreamNonBlocking);
    cudaEventCreateWithFlags(&evStart, cudaEventDisableTiming);
    cudaEventCreateWithFlags(&evWz, cudaEventDisableTiming);
    cudaEventCreateWithFlags(&evWzT, cudaEventDisableTiming);
    for (int i = 0; i < 10; i++) {
      cudaEventCreateWithFlags(&evBw[i], cudaEventDisableTiming);
      cudaEventCreateWithFlags(&evTail[i], cudaEventDisableTiming);
    }
    cudaFuncSetAttribute(mma_gemm<2>, cudaFuncAttributeMaxDynamicSharedMemorySize, SMEM_SZ);
    cudaFuncSetAttribute(mma_gemm<3>, cudaFuncAttributeMaxDynamicSharedMemorySize, SMEM_SZ);
    cudaFuncSetAttribute(mma_gemm<4>, cudaFuncAttributeMaxDynamicSharedMemorySize, SMEM_SZ);
    cudaFuncSetAttribute(head_gemm, cudaFuncAttributeMaxDynamicSharedMemorySize, SMEM_SZ);
    s_init = true;
  }

  // ---- fork side streams ----
  cudaEventRecord(evStart, 0);
  cudaStreamWaitEvent(st1, evStart, 0);
  cudaStreamWaitEvent(st2, evStart, 0);

  // s1: Wz split (fwd) + Wz transpose split (bwd)
  k_split<<<((Ll - 1) * Hh * Hh + 255) / 256, 256, 0, st1>>>(
      Wz, Wzh, Wzl, (Ll - 1) * Hh * Hh);
  cudaEventRecord(evWz, st1);
  k_wzT<<<((Ll - 1) * Hh * Hh + 255) / 256, 256, 0, st1>>>(Wz, WzTh, WzTl);
  cudaEventRecord(evWzT, st1);

  // s2: tail weights + dot + gx zero
  k_bcat<<<(Ll * Dd * 1024 + 255) / 256, 256, 0, st2>>>(Wq, Wl, Bch, Bcl);
  k_dotzero<<<(Bsz * Dd + 255) / 256, 256, 0, st2>>>(x, wq_out, S, gx);

  // s0: input/weight splits then fused head
  {
    int tot = Bsz * Dd + 2 * LH * Dd;
    k_split3<<<(tot + 255) / 256, 256>>>(x, Wq, Wl, xh, xl, Wqh, Wql, Wlh, Wll);
  }
  head_gemm<<<dim3(LH / 64, Bsz / 128), 256, SMEM_SZ>>>(
      xh, xl, Wqh, Wql, Wlh, Wll, bl, U, P, F, zAh, zAl);

  // ---- forward chain ----
  bf16* zh2[2] = {zAh, zBh};
  bf16* zl2[2] = {zAl, zBl};
  cudaStreamWaitEvent(0, evWz, 0);
  for (int l = 1; l < Ll; ++l) {
    EpiP ep = {};
    ep.Pc = P;
    ep.F = F;
    ep.coff = l * Hh;
    ep.zh = zh2[l & 1];
    ep.zl = zl2[l & 1];
    mma_gemm<2><<<dim3(Hh / 128, Bsz / 128, 1), 256, SMEM_SZ>>>(
        zh2[(l - 1) & 1], zl2[(l - 1) & 1], Wzh + (size_t)(l - 1) * Hh * Hh,
        Wzl + (size_t)(l - 1) * Hh * Hh, Hh, Hh, Hh, ep);
  }

  // ---- backward init (layer 9) -> ga9 in zh2[0], Acat buf[1] ----
  k_bwinit<<<(Bsz * Hh + 255) / 256, 256>>>(F, U, wz_out, zh2[0], zl2[0],
                                            Ach[1], Acl[1]);
  cudaEventRecord(evBw[9], 0);

  // tail 9 on s2 (s2 already did bcat + dotzero in order)
  cudaStreamWaitEvent(st2, evBw[9], 0);
  {
    EpiP ep = {};
    ep.gx = gx;
    mma_gemm<4><<<dim3(1, Bsz / 128, 2), 256, SMEM_SZ, st2>>>(
        Ach[1], Acl[1], Bch + (size_t)(Ll - 1) * Dd * 1024,
        Bcl + (size_t)(Ll - 1) * Dd * 1024, 512, 1024, 1024, ep);
    cudaEventRecord(evTail[9], st2);
  }

  // ---- backward chain on s0, tails on s2 ----
  cudaStreamWaitEvent(0, evWzT, 0);
  int cur = 0;
  for (int l = Ll - 2; l >= 0; --l) {
    if (l + 2 <= 9) cudaStreamWaitEvent(0, evTail[l + 2], 0);  // buf reuse guard
    {
      EpiP ep = {};
      ep.F = F;
      ep.U = U;
      ep.coff = l * Hh;
      ep.zh = zh2[cur ^ 1];
      ep.zl = zl2[cur ^ 1];
      ep.ach = Ach[l & 1];
      ep.acl = Acl[l & 1];
      mma_gemm<3><<<dim3(Hh / 128, Bsz / 128, 1), 256, SMEM_SZ>>>(
          zh2[cur], zl2[cur], WzTh + (size_t)l * Hh * Hh,
          WzTl + (size_t)l * Hh * Hh, Hh, Hh, Hh, ep);
      cur ^= 1;
    }
    cudaEventRecord(evBw[l], 0);
    cudaStreamWaitEvent(st2, evBw[l], 0);
    {
      EpiP ep = {};
      ep.gx = gx;
      mma_gemm<4><<<dim3(1, Bsz / 128, 2), 256, SMEM_SZ, st2>>>(
          Ach[l & 1], Acl[l & 1], Bch + (size_t)l * Dd * 1024,
          Bcl + (size_t)l * Dd * 1024, 512, 1024, 1024, ep);
      cudaEventRecord(evTail[l], st2);
    }
  }

  // ---- join and final combine ----
  cudaStreamWaitEvent(0, evTail[0], 0);
  k_final<<<(Bsz * Dd + 255) / 256, 256>>>(gx, S, wq_out, wl_out, x, out);
}

// round 5
// speedup vs baseline: 2.7228x; 1.3410x over previous
#include <cuda_runtime.h>
#include <cuda_bf16.h>
#include <cstdint>

// ===========================================================================
// ICNN forward + input-gradient via mma.sync bf16 (2-way split, 3 products).
// Round 5: smem-staged coalesced epilogues for all GEMMs (removes ~4x
// store/load amplification of fragment-scattered epilogues).
// ===========================================================================

typedef __nv_bfloat16 bf16;

#define NEG_SLOPE 0.2f
constexpr int Bsz = 8192;
constexpr int Dd  = 128;
constexpr int Hh  = 512;
constexpr int Ll  = 10;
constexpr int LH  = Ll * Hh;  // 5120

// ---------------- static device scratch ------------------------------------
__device__ bf16 g_xh[(size_t)Bsz * Dd], g_xl[(size_t)Bsz * Dd];
__device__ bf16 g_Wqh[(size_t)LH * Dd], g_Wql[(size_t)LH * Dd];
__device__ bf16 g_Wlh[(size_t)LH * Dd], g_Wll[(size_t)LH * Dd];
__device__ bf16 g_Wzh[(size_t)(Ll - 1) * Hh * Hh], g_Wzl[(size_t)(Ll - 1) * Hh * Hh];
__device__ bf16 g_WzTh[(size_t)(Ll - 1) * Hh * Hh], g_WzTl[(size_t)(Ll - 1) * Hh * Hh];
__device__ bf16 g_Bch[(size_t)Ll * Dd * 1024], g_Bcl[(size_t)Ll * Dd * 1024];
__device__ float g_U[(size_t)Bsz * LH];
__device__ float g_P[(size_t)Bsz * LH];
__device__ unsigned char g_F[(size_t)Bsz * LH];
__device__ bf16 g_zAh[(size_t)Bsz * Hh], g_zAl[(size_t)Bsz * Hh];
__device__ bf16 g_zBh[(size_t)Bsz * Hh], g_zBl[(size_t)Bsz * Hh];
__device__ bf16 g_Ach0[(size_t)Bsz * 1024], g_Acl0[(size_t)Bsz * 1024];
__device__ bf16 g_Ach1[(size_t)Bsz * 1024], g_Acl1[(size_t)Bsz * 1024];
__device__ float g_gx[(size_t)Bsz * Dd];
__device__ float g_S[Bsz];

// ---------------- helpers ---------------------------------------------------
__device__ __forceinline__ uint32_t smem_u32(const void* p) {
  uint32_t a;
  asm("{ .reg .u64 t; cvta.to.shared.u64 t, %1; cvt.u32.u64 %0, t; }"
      : "=r"(a) : "l"(p));
  return a;
}
__device__ __forceinline__ void cpa16(uint32_t s, const void* g) {
  asm volatile("cp.async.cg.shared.global [%0], [%1], 16;" ::"r"(s), "l"(g));
}
__device__ __forceinline__ void cpa_commit() {
  asm volatile("cp.async.commit_group;" ::: "memory");
}
__device__ __forceinline__ void cpa_wait0() {
  asm volatile("cp.async.wait_group 0;" ::: "memory");
}
__device__ __forceinline__ void ldsm4(uint32_t addr, uint32_t* r) {
  asm volatile("ldmatrix.sync.aligned.m8n8.x4.shared.b16 {%0,%1,%2,%3}, [%4];"
               : "=r"(r[0]), "=r"(r[1]), "=r"(r[2]), "=r"(r[3]) : "r"(addr));
}
__device__ __forceinline__ void mma16816(float* c, const uint32_t* a,
                                         const uint32_t* b) {
  asm volatile(
      "mma.sync.aligned.m16n8k16.row.col.f32.bf16.bf16.f32 "
      "{%0,%1,%2,%3}, {%4,%5,%6,%7}, {%8,%9}, {%0,%1,%2,%3};"
      : "+f"(c[0]), "+f"(c[1]), "+f"(c[2]), "+f"(c[3])
      : "r"(a[0]), "r"(a[1]), "r"(a[2]), "r"(a[3]), "r"(b[0]), "r"(b[1]));
}
__device__ __forceinline__ void bsplit(float v, bf16& h, bf16& l) {
  h = __float2bfloat16(v);
  l = __float2bfloat16(v - __bfloat162float(h));
}

// ---------------- epilogue params -------------------------------------------
struct EpiP {
  const float* U;
  const float* Pc;
  unsigned char* F;
  bf16* zh;
  bf16* zl;
  bf16* ach;
  bf16* acl;
  float* gx;
  int coff;
};

// Vectorized epilogue for 2 consecutive columns (n even).
// EPI: 2=fwd layer; 3=bwd layer; 4=gx accum
template <int EPI>
__device__ __forceinline__ void epi_pair(int m, int n, float d0, float d1,
                                         const EpiP& ep) {
  if (EPI == 2) {
    size_t idx = (size_t)m * LH + ep.coff + n;
    float2 pc = *reinterpret_cast<const float2*>(&ep.Pc[idx]);
    float a0 = d0 + pc.x, a1 = d1 + pc.y;
    bool p0 = (a0 >= 0.f), p1 = (a1 >= 0.f);
    uchar2 f2;
    f2.x = p0 ? 1 : 0;
    f2.y = p1 ? 1 : 0;
    *reinterpret_cast<uchar2*>(&ep.F[idx]) = f2;
    float z0 = p0 ? a0 : NEG_SLOPE * a0;
    float z1 = p1 ? a1 : NEG_SLOPE * a1;
    bf16 h0, l0, h1, l1;
    bsplit(z0, h0, l0);
    bsplit(z1, h1, l1);
    __nv_bfloat162 hv, lv;
    hv.x = h0; hv.y = h1;
    lv.x = l0; lv.y = l1;
    *reinterpret_cast<__nv_bfloat162*>(&ep.zh[(size_t)m * Hh + n]) = hv;
    *reinterpret_cast<__nv_bfloat162*>(&ep.zl[(size_t)m * Hh + n]) = lv;
  } else if (EPI == 3) {
    size_t idx = (size_t)m * LH + ep.coff + n;
    uchar2 f2 = *reinterpret_cast<const uchar2*>(&ep.F[idx]);
    float f0 = f2.x ? 1.f : NEG_SLOPE;
    float f1 = f2.y ? 1.f : NEG_SLOPE;
    float ga0 = d0 * f0, ga1 = d1 * f1;
    float2 uu = *reinterpret_cast<const float2*>(&ep.U[idx]);
    float g10 = 2.f * ga0 * uu.x, g11 = 2.f * ga1 * uu.y;
    bf16 gh0, gl0, gh1, gl1, h10, l10, h11, l11;
    bsplit(ga0, gh0, gl0);
    bsplit(ga1, gh1, gl1);
    bsplit(g10, h10, l10);
    bsplit(g11, h11, l11);
    __nv_bfloat162 v;
    v.x = gh0; v.y = gh1;
    *reinterpret_cast<__nv_bfloat162*>(&ep.zh[(size_t)m * Hh + n]) = v;
    v.x = gl0; v.y = gl1;
    *reinterpret_cast<__nv_bfloat162*>(&ep.zl[(size_t)m * Hh + n]) = v;
    size_t ai = (size_t)m * 1024 + n;
    v.x = h10; v.y = h11;
    *reinterpret_cast<__nv_bfloat162*>(&ep.ach[ai]) = v;
    v.x = l10; v.y = l11;
    *reinterpret_cast<__nv_bfloat162*>(&ep.acl[ai]) = v;
    v.x = gh0; v.y = gh1;
    *reinterpret_cast<__nv_bfloat162*>(&ep.ach[ai + Hh]) = v;
    v.x = gl0; v.y = gl1;
    *reinterpret_cast<__nv_bfloat162*>(&ep.acl[ai + Hh]) = v;
  } else {  // EPI == 4
    atomicAdd(&ep.gx[(size_t)m * Dd + n], d0);
    atomicAdd(&ep.gx[(size_t)m * Dd + n + 1], d1);
  }
}

// ---------------- chain / tail GEMM -----------------------------------------
// C[128,128]/CTA = (Ah+Al)[M,K] @ (Bh+Bl)[N,K]^T, 3 bf16 products.
// 8 warps, warp tile 32x64. BK=32 double-buffered cp.async.
// Epilogue staged through smem for coalesced global access.
template <int EPI>
__global__ __launch_bounds__(256) void mma_gemm(
    const bf16* __restrict__ Ah, const bf16* __restrict__ Al,
    const bf16* __restrict__ Bh, const bf16* __restrict__ Bl, int Kc, int lda,
    int ldb, EpiP ep) {
  extern __shared__ char smc[];
  const uint32_t sb = smem_u32(smc);
  const int tid = threadIdx.x, lane = tid & 31, wid = tid >> 5;
  const int m0 = blockIdx.y * 128, n0 = blockIdx.x * 128;
  const int wm = (wid & 3) * 32, wn = (wid >> 2) * 64;
  const int kstart = blockIdx.z * Kc;
  constexpr uint32_t PL = 10240;
  constexpr uint32_t STG = 40960;

  const int lr = tid >> 1;
  const int lc = (tid & 1) * 2;

  const bf16* pA0 = Ah + (size_t)(m0 + lr) * lda + lc * 8;
  const bf16* pA1 = Al + (size_t)(m0 + lr) * lda + lc * 8;
  const bf16* pB0 = Bh + (size_t)(n0 + lr) * ldb + lc * 8;
  const bf16* pB1 = Bl + (size_t)(n0 + lr) * ldb + lc * 8;

  auto stage_load = [&](int s, int k0) {
    uint32_t base = sb + (uint32_t)s * STG + (uint32_t)lr * 80 + lc * 16;
    cpa16(base, pA0 + k0);
    cpa16(base + 16, pA0 + k0 + 8);
    cpa16(base + PL, pA1 + k0);
    cpa16(base + PL + 16, pA1 + k0 + 8);
    cpa16(base + 2 * PL, pB0 + k0);
    cpa16(base + 2 * PL + 16, pB0 + k0 + 8);
    cpa16(base + 3 * PL, pB1 + k0);
    cpa16(base + 3 * PL + 16, pB1 + k0 + 8);
    cpa_commit();
  };

  float acc[2][8][4];
#pragma unroll
  for (int i = 0; i < 2; i++)
#pragma unroll
    for (int j = 0; j < 8; j++)
#pragma unroll
      for (int q = 0; q < 4; q++) acc[i][j][q] = 0.f;

  const int nk = Kc / 32;
  stage_load(0, kstart);
  cpa_wait0();
  __syncthreads();

  const int g3 = lane >> 3, r8 = lane & 7;

  for (int kb = 0; kb < nk; ++kb) {
    const int s = kb & 1;
    if (kb + 1 < nk) stage_load(s ^ 1, kstart + (kb + 1) * 32);
    const uint32_t ab = sb + (uint32_t)s * STG;
#pragma unroll
    for (int k16 = 0; k16 < 32; k16 += 16) {
      uint32_t Ahf[2][4], Alf[2][4], Bhf[8][2], Blf[8][2];
#pragma unroll
      for (int mi = 0; mi < 2; mi++) {
        uint32_t row = wm + mi * 16 + (g3 & 1) * 8 + r8;
        uint32_t col = k16 + (g3 >> 1) * 8;
        uint32_t ad = ab + row * 80 + col * 2;
        ldsm4(ad, Ahf[mi]);
        ldsm4(ad + PL, Alf[mi]);
      }
#pragma unroll
      for (int pi = 0; pi < 4; pi++) {
        uint32_t row = wn + (2 * pi + (g3 >> 1)) * 8 + r8;
        uint32_t col = k16 + (g3 & 1) * 8;
        uint32_t ad = ab + 2 * PL + row * 80 + col * 2;
        uint32_t t[4];
        ldsm4(ad, t);
        Bhf[2 * pi][0] = t[0];
        Bhf[2 * pi][1] = t[1];
        Bhf[2 * pi + 1][0] = t[2];
        Bhf[2 * pi + 1][1] = t[3];
        ldsm4(ad + PL, t);
        Blf[2 * pi][0] = t[0];
        Blf[2 * pi][1] = t[1];
        Blf[2 * pi + 1][0] = t[2];
        Blf[2 * pi + 1][1] = t[3];
      }
#pragma unroll
      for (int mi = 0; mi < 2; mi++)
#pragma unroll
        for (int ni = 0; ni < 8; ni++) {
          mma16816(acc[mi][ni], Ahf[mi], Bhf[ni]);
          mma16816(acc[mi][ni], Ahf[mi], Blf[ni]);
          mma16816(acc[mi][ni], Alf[mi], Bhf[ni]);
        }
    }
    cpa_wait0();
    __syncthreads();
  }

  // ---- stage accumulators to smem ----
  float* cs = reinterpret_cast<float*>(smc);
  const int g = lane >> 2, t4 = lane & 3;
#pragma unroll
  for (int mi = 0; mi < 2; mi++)
#pragma unroll
    for (int ni = 0; ni < 8; ni++) {
      int r = wm + mi * 16 + g;
      int c = wn + ni * 8 + t4 * 2;
      *reinterpret_cast<float2*>(&cs[r * 132 + c]) =
          make_float2(acc[mi][ni][0], acc[mi][ni][1]);
      *reinterpret_cast<float2*>(&cs[(r + 8) * 132 + c]) =
          make_float2(acc[mi][ni][2], acc[mi][ni][3]);
    }
  __syncthreads();

  // ---- coalesced epilogue: warp wid handles rows [wid*16, wid*16+16) ----
#pragma unroll 4
  for (int rr = 0; rr < 16; ++rr) {
    int row = wid * 16 + rr;
    int m = m0 + row;
#pragma unroll
    for (int i = 0; i < 2; ++i) {
      int c = 2 * lane + 64 * i;
      float d0 = cs[row * 132 + c];
      float d1 = cs[row * 132 + c + 1];
      epi_pair<EPI>(m, n0 + c, d0, d1, ep);
    }
  }
}

// ---------------- fused head GEMM -------------------------------------------
// One pass: U = x@Wq^T, P = U^2 + x@Wl^T + bl, z0/F for n<Hh.
// CTA tile 128(m) x 64(n), dual accumulators, 8 warps warp-tile 32x32.
__global__ __launch_bounds__(256) void head_gemm(
    const bf16* __restrict__ Axh, const bf16* __restrict__ Axl,
    const bf16* __restrict__ Wqh, const bf16* __restrict__ Wql,
    const bf16* __restrict__ Wlh, const bf16* __restrict__ Wll,
    const float* __restrict__ blv, float* __restrict__ U,
    float* __restrict__ P, unsigned char* __restrict__ F,
    bf16* __restrict__ zh, bf16* __restrict__ zl) {
  extern __shared__ char smc[];
  const uint32_t sb = smem_u32(smc);
  const int tid = threadIdx.x, lane = tid & 31, wid = tid >> 5;
  const int m0 = blockIdx.y * 128, n0 = blockIdx.x * 64;
  const int wm = (wid & 3) * 32, wn = (wid >> 2) * 32;
  constexpr uint32_t PA = 10240;
  constexpr uint32_t PB = 5120;
  constexpr uint32_t STG = 2 * PA + 4 * PB;  // 40960

  const int lr = tid >> 1, lc = (tid & 1) * 2;
  const bf16* pA0 = Axh + (size_t)(m0 + lr) * Dd + lc * 8;
  const bf16* pA1 = Axl + (size_t)(m0 + lr) * Dd + lc * 8;
  const int br = (tid & 127) >> 1, bcp = (tid & 1) * 2;
  const int bw = tid >> 7;
  const bf16* pB0 = (bw ? Wlh : Wqh) + (size_t)(n0 + br) * Dd + bcp * 8;
  const bf16* pB1 = (bw ? Wll : Wql) + (size_t)(n0 + br) * Dd + bcp * 8;
  const uint32_t bOff = 2 * PA + (uint32_t)bw * 2 * PB + (uint32_t)br * 80 + bcp * 16;

  auto stage_load = [&](int s, int k0) {
    uint32_t base = sb + (uint32_t)s * STG;
    uint32_t aA = base + (uint32_t)lr * 80 + lc * 16;
    cpa16(aA, pA0 + k0);
    cpa16(aA + 16, pA0 + k0 + 8);
    cpa16(aA + PA, pA1 + k0);
    cpa16(aA + PA + 16, pA1 + k0 + 8);
    uint32_t aB = base + bOff;
    cpa16(aB, pB0 + k0);
    cpa16(aB + 16, pB0 + k0 + 8);
    cpa16(aB + PB, pB1 + k0);
    cpa16(aB + PB + 16, pB1 + k0 + 8);
    cpa_commit();
  };

  float accq[2][4][4], accl[2][4][4];
#pragma unroll
  for (int i = 0; i < 2; i++)
#pragma unroll
    for (int j = 0; j < 4; j++)
#pragma unroll
      for (int q = 0; q < 4; q++) accq[i][j][q] = accl[i][j][q] = 0.f;

  constexpr int nk = Dd / 32;
  stage_load(0, 0);
  cpa_wait0();
  __syncthreads();

  const int g3 = lane >> 3, r8 = lane & 7;

  for (int kb = 0; kb < nk; ++kb) {
    const int s = kb & 1;
    if (kb + 1 < nk) stage_load(s ^ 1, (kb + 1) * 32);
    const uint32_t ab = sb + (uint32_t)s * STG;
#pragma unroll
    for (int k16 = 0; k16 < 32; k16 += 16) {
      uint32_t Ahf[2][4], Alf[2][4];
      uint32_t Bqh_[4][2], Bql_[4][2], Blh_[4][2], Bll_[4][2];
#pragma unroll
      for (int mi = 0; mi < 2; mi++) {
        uint32_t row = wm + mi * 16 + (g3 & 1) * 8 + r8;
        uint32_t col = k16 + (g3 >> 1) * 8;
        uint32_t ad = ab + row * 80 + col * 2;
        ldsm4(ad, Ahf[mi]);
        ldsm4(ad + PA, Alf[mi]);
      }
#pragma unroll
      for (int pi = 0; pi < 2; pi++) {
        uint32_t row = wn + (2 * pi + (g3 >> 1)) * 8 + r8;
        uint32_t col = k16 + (g3 & 1) * 8;
        uint32_t adq = ab + 2 * PA + row * 80 + col * 2;
        uint32_t t[4];
        ldsm4(adq, t);
        Bqh_[2 * pi][0] = t[0]; Bqh_[2 * pi][1] = t[1];
        Bqh_[2 * pi + 1][0] = t[2]; Bqh_[2 * pi + 1][1] = t[3];
        ldsm4(adq + PB, t);
        Bql_[2 * pi][0] = t[0]; Bql_[2 * pi][1] = t[1];
        Bql_[2 * pi + 1][0] = t[2]; Bql_[2 * pi + 1][1] = t[3];
        ldsm4(adq + 2 * PB, t);
        Blh_[2 * pi][0] = t[0]; Blh_[2 * pi][1] = t[1];
        Blh_[2 * pi + 1][0] = t[2]; Blh_[2 * pi + 1][1] = t[3];
        ldsm4(adq + 3 * PB, t);
        Bll_[2 * pi][0] = t[0]; Bll_[2 * pi][1] = t[1];
        Bll_[2 * pi + 1][0] = t[2]; Bll_[2 * pi + 1][1] = t[3];
      }
#pragma unroll
      for (int mi = 0; mi < 2; mi++)
#pragma unroll
        for (int ni = 0; ni < 4; ni++) {
          mma16816(accq[mi][ni], Ahf[mi], Bqh_[ni]);
          mma16816(accq[mi][ni], Ahf[mi], Bql_[ni]);
          mma16816(accq[mi][ni], Alf[mi], Bqh_[ni]);
          mma16816(accl[mi][ni], Ahf[mi], Blh_[ni]);
          mma16816(accl[mi][ni], Ahf[mi], Bll_[ni]);
          mma16816(accl[mi][ni], Alf[mi], Blh_[ni]);
        }
    }
    cpa_wait0();
    __syncthreads();
  }

  // ---- stage both tiles to smem: cols [0,64)=U acc, [64,128)=V acc ----
  float* cs = reinterpret_cast<float*>(smc);
  const int g = lane >> 2, t4 = lane & 3;
#pragma unroll
  for (int mi = 0; mi < 2; mi++)
#pragma unroll
    for (int ni = 0; ni < 4; ni++) {
      int r = wm + mi * 16 + g;
      int c = wn + ni * 8 + t4 * 2;
      *reinterpret_cast<float2*>(&cs[r * 132 + c]) =
          make_float2(accq[mi][ni][0], accq[mi][ni][1]);
      *reinterpret_cast<float2*>(&cs[(r + 8) * 132 + c]) =
          make_float2(accq[mi][ni][2], accq[mi][ni][3]);
      *reinterpret_cast<float2*>(&cs[r * 132 + 64 + c]) =
          make_float2(accl[mi][ni][0], accl[mi][ni][1]);
      *reinterpret_cast<float2*>(&cs[(r + 8) * 132 + 64 + c]) =
          make_float2(accl[mi][ni][2], accl[mi][ni][3]);
    }
  __syncthreads();

  const bool inZ = (n0 < Hh);  // uniform per CTA
#pragma unroll 4
  for (int rr = 0; rr < 16; ++rr) {
    int row = wid * 16 + rr;
    int m = m0 + row;
    int c = 2 * lane;
    int n = n0 + c;
    float u0 = cs[row * 132 + c], u1 = cs[row * 132 + c + 1];
    float v0 = cs[row * 132 + 64 + c], v1 = cs[row * 132 + 64 + c + 1];
    size_t idx = (size_t)m * LH + n;
    *reinterpret_cast<float2*>(&U[idx]) = make_float2(u0, u1);
    float2 b2 = *reinterpret_cast<const float2*>(&blv[n]);
    float p0 = u0 * u0 + v0 + b2.x;
    float p1 = u1 * u1 + v1 + b2.y;
    *reinterpret_cast<float2*>(&P[idx]) = make_float2(p0, p1);
    if (inZ) {
      bool s0 = (p0 >= 0.f), s1 = (p1 >= 0.f);
      uchar2 f2;
      f2.x = s0 ? 1 : 0;
      f2.y = s1 ? 1 : 0;
      *reinterpret_cast<uchar2*>(&F[idx]) = f2;
      float z0 = s0 ? p0 : NEG_SLOPE * p0;
      float z1 = s1 ? p1 : NEG_SLOPE * p1;
      bf16 h0, l0, h1, l1;
      bsplit(z0, h0, l0);
      bsplit(z1, h1, l1);
      __nv_bfloat162 hv, lv;
      hv.x = h0; hv.y = h1;
      lv.x = l0; lv.y = l1;
      *reinterpret_cast<__nv_bfloat162*>(&zh[(size_t)m * Hh + n]) = hv;
      *reinterpret_cast<__nv_bfloat162*>(&zl[(size_t)m * Hh + n]) = lv;
    }
  }
}

// ---------------- prep / elementwise ----------------------------------------
__global__ void k_split3(const float* __restrict__ x, const float* __restrict__ Wq,
                         const float* __restrict__ Wl, bf16* __restrict__ xh,
                         bf16* __restrict__ xl, bf16* __restrict__ qh,
                         bf16* __restrict__ ql, bf16* __restrict__ lh,
                         bf16* __restrict__ ll) {
  int i = blockIdx.x * 256 + threadIdx.x;
  const int n1 = Bsz * Dd, n2 = LH * Dd;
  bf16 h, l;
  if (i < n1) {
    bsplit(x[i], h, l);
    xh[i] = h; xl[i] = l;
  } else if (i < n1 + n2) {
    int j = i - n1;
    bsplit(Wq[j], h, l);
    qh[j] = h; ql[j] = l;
  } else if (i < n1 + 2 * n2) {
    int j = i - n1 - n2;
    bsplit(Wl[j], h, l);
    lh[j] = h; ll[j] = l;
  }
}

__global__ void k_split(const float* __restrict__ in, bf16* __restrict__ h,
                        bf16* __restrict__ l, int n) {
  int i = blockIdx.x * 256 + threadIdx.x;
  if (i < n) {
    bf16 hh, ll;
    bsplit(in[i], hh, ll);
    h[i] = hh;
    l[i] = ll;
  }
}

__global__ void k_wzT(const float* __restrict__ Wz, bf16* __restrict__ h,
                      bf16* __restrict__ l) {
  int i = blockIdx.x * 256 + threadIdx.x;
  int lay = i / (Hh * Hh);
  int r = i % (Hh * Hh);
  int o = r / Hh, ii = r % Hh;
  size_t dst = (size_t)lay * Hh * Hh + (size_t)ii * Hh + o;
  bf16 hh, ll;
  bsplit(Wz[i], hh, ll);
  h[dst] = hh;
  l[dst] = ll;
}

__global__ void k_bcat(const float* __restrict__ Wq, const float* __restrict__ Wl,
                       bf16* __restrict__ h, bf16* __restrict__ l) {
  int i = blockIdx.x * 256 + threadIdx.x;
  int lay = i / (Dd * 1024);
  int r = i % (Dd * 1024);
  int d = r / 1024, k = r % 1024;
  float v = (k < Hh) ? Wq[((size_t)lay * Hh + k) * Dd + d]
                     : Wl[((size_t)lay * Hh + (k - Hh)) * Dd + d];
  bf16 hh, ll;
  bsplit(v, hh, ll);
  h[i] = hh;
  l[i] = ll;
}

__global__ void k_dotzero(const float* __restrict__ x, const float* __restrict__ wq,
                          float* __restrict__ S, float* __restrict__ gx) {
  int gid = blockIdx.x * 256 + threadIdx.x;
  if (gid < Bsz * Dd) gx[gid] = 0.f;
  int w = gid / 32, lane = gid % 32;
  if (w < Bsz) {
    float s = 0.f;
    for (int d = lane; d < Dd; d += 32) s += x[(size_t)w * Dd + d] * wq[d];
#pragma unroll
    for (int o = 16; o; o >>= 1) s += __shfl_xor_sync(0xFFFFFFFFu, s, o);
    if (lane == 0) S[w] = s;
  }
}

__global__ void k_bwinit(const unsigned char* __restrict__ F,
                         const float* __restrict__ U,
                         const float* __restrict__ wz_out,
                         bf16* __restrict__ zh, bf16* __restrict__ zl,
                         bf16* __restrict__ ach, bf16* __restrict__ acl) {
  int i = blockIdx.x * 256 + threadIdx.x;
  int m = i / Hh, h = i % Hh;
  size_t idx = (size_t)m * LH + (size_t)(Ll - 1) * Hh + h;
  float f = F[idx] ? 1.f : NEG_SLOPE;
  float ga = wz_out[h] * f;
  bf16 gh, gl;
  bsplit(ga, gh, gl);
  zh[i] = gh;
  zl[i] = gl;
  float g1 = 2.f * ga * U[idx];
  bf16 h1, l1;
  bsplit(g1, h1, l1);
  size_t ai = (size_t)m * 1024 + h;
  ach[ai] = h1;
  acl[ai] = l1;
  ach[ai + Hh] = gh;
  acl[ai + Hh] = gl;
}

__global__ void k_final(const float* __restrict__ gx, const float* __restrict__ S,
                        const float* __restrict__ wq, const float* __restrict__ wl,
                        const float* __restrict__ x, float* __restrict__ out) {
  int i = blockIdx.x * 256 + threadIdx.x;
  int m = i >> 7, n = i & 127;
  out[i] = 0.5f * (gx[i] + 2.f * S[m] * wq[n] + wl[n]) + 0.5f * x[i];
}

// ---------------- host driver ------------------------------------------------
constexpr uint32_t SMEM_SZ = 81920;

extern "C" void kernel_launch(void* const* d_in, const int* in_sizes, int n_in,
                              void* d_out, int out_size) {
  const float* x = (const float*)d_in[0];
  const float* Wq = (const float*)d_in[1];
  const float* Wl = (const float*)d_in[2];
  const float* bl = (const float*)d_in[3];
  const float* Wz = (const float*)d_in[4];
  const float* wz_out = (const float*)d_in[5];
  const float* wq_out = (const float*)d_in[6];
  const float* wl_out = (const float*)d_in[7];
  float* out = (float*)d_out;

  bf16 *xh, *xl, *Wqh, *Wql, *Wlh, *Wll, *Wzh, *Wzl, *WzTh, *WzTl, *Bch, *Bcl;
  bf16 *zAh, *zAl, *zBh, *zBl;
  bf16 *Ach[2], *Acl[2];
  float *U, *P, *gx, *S;
  unsigned char* F;
  cudaGetSymbolAddress((void**)&xh, g_xh);
  cudaGetSymbolAddress((void**)&xl, g_xl);
  cudaGetSymbolAddress((void**)&Wqh, g_Wqh);
  cudaGetSymbolAddress((void**)&Wql, g_Wql);
  cudaGetSymbolAddress((void**)&Wlh, g_Wlh);
  cudaGetSymbolAddress((void**)&Wll, g_Wll);
  cudaGetSymbolAddress((void**)&Wzh, g_Wzh);
  cudaGetSymbolAddress((void**)&Wzl, g_Wzl);
  cudaGetSymbolAddress((void**)&WzTh, g_WzTh);
  cudaGetSymbolAddress((void**)&WzTl, g_WzTl);
  cudaGetSymbolAddress((void**)&Bch, g_Bch);
  cudaGetSymbolAddress((void**)&Bcl, g_Bcl);
  cudaGetSymbolAddress((void**)&U, g_U);
  cudaGetSymbolAddress((void**)&P, g_P);
  cudaGetSymbolAddress((void**)&F, g_F);
  cudaGetSymbolAddress((void**)&zAh, g_zAh);
  cudaGetSymbolAddress((void**)&zAl, g_zAl);
  cudaGetSymbolAddress((void**)&zBh, g_zBh);
  cudaGetSymbolAddress((void**)&zBl, g_zBl);
  cudaGetSymbolAddress((void**)&Ach[0], g_Ach0);
  cudaGetSymbolAddress((void**)&Acl[0], g_Acl0);
  cudaGetSymbolAddress((void**)&Ach[1], g_Ach1);
  cudaGetSymbolAddress((void**)&Acl[1], g_Acl1);
  cudaGetSymbolAddress((void**)&gx, g_gx);
  cudaGetSymbolAddress((void**)&S, g_S);

  static bool s_init = false;
  static cudaStream_t st1, st2;
  static cudaEvent_t evStart, evWz, evWzT, evBw[10], evTail[10];
  if (!s_init) {
    cudaStreamCreateWithFlags(&st1, cudaStreamNonBlocking);
    cudaStreamCreateWithFlags(&st2, cudaStreamNonBlocking);
    cudaEventCreateWithFlags(&evStart, cudaEventDisableTiming);
    cudaEventCreateWithFlags(&evWz, cudaEventDisableTiming);
    cudaEventCreateWithFlags(&evWzT, cudaEventDisableTiming);
    for (int i = 0; i < 10; i++) {
      cudaEventCreateWithFlags(&evBw[i], cudaEventDisableTiming);
      cudaEventCreateWithFlags(&evTail[i], cudaEventDisableTiming);
    }
    cudaFuncSetAttribute(mma_gemm<2>, cudaFuncAttributeMaxDynamicSharedMemorySize, SMEM_SZ);
    cudaFuncSetAttribute(mma_gemm<3>, cudaFuncAttributeMaxDynamicSharedMemorySize, SMEM_SZ);
    cudaFuncSetAttribute(mma_gemm<4>, cudaFuncAttributeMaxDynamicSharedMemorySize, SMEM_SZ);
    cudaFuncSetAttribute(head_gemm, cudaFuncAttributeMaxDynamicSharedMemorySize, SMEM_SZ);
    s_init = true;
  }

  // ---- fork side streams ----
  cudaEventRecord(evStart, 0);
  cudaStreamWaitEvent(st1, evStart, 0);
  cudaStreamWaitEvent(st2, evStart, 0);

  // launch 0: input/weight splits (s0)
  {
    int tot = Bsz * Dd + 2 * LH * Dd;
    k_split3<<<(tot + 255) / 256, 256>>>(x, Wq, Wl, xh, xl, Wqh, Wql, Wlh, Wll);
  }
  // launch 1: Wz split (st1)
  k_split<<<((Ll - 1) * Hh * Hh + 255) / 256, 256, 0, st1>>>(
      Wz, Wzh, Wzl, (Ll - 1) * Hh * Hh);
  cudaEventRecord(evWz, st1);

  // launch 2: fused head
  head_gemm<<<dim3(LH / 64, Bsz / 128), 256, SMEM_SZ>>>(
      xh, xl, Wqh, Wql, Wlh, Wll, bl, U, P, F, zAh, zAl);

  // launches 3..11: forward chain (ncu -s 5 lands here)
  bf16* zh2[2] = {zAh, zBh};
  bf16* zl2[2] = {zAl, zBl};
  cudaStreamWaitEvent(0, evWz, 0);
  for (int l = 1; l < Ll; ++l) {
    EpiP ep = {};
    ep.Pc = P;
    ep.F = F;
    ep.coff = l * Hh;
    ep.zh = zh2[l & 1];
    ep.zl = zl2[l & 1];
    mma_gemm<2><<<dim3(Hh / 128, Bsz / 128, 1), 256, SMEM_SZ>>>(
        zh2[(l - 1) & 1], zl2[(l - 1) & 1], Wzh + (size_t)(l - 1) * Hh * Hh,
        Wzl + (size_t)(l - 1) * Hh * Hh, Hh, Hh, Hh, ep);
  }

  // side-stream preps (overlap with chain on device)
  k_wzT<<<((Ll - 1) * Hh * Hh + 255) / 256, 256, 0, st1>>>(Wz, WzTh, WzTl);
  cudaEventRecord(evWzT, st1);
  k_bcat<<<(Ll * Dd * 1024 + 255) / 256, 256, 0, st2>>>(Wq, Wl, Bch, Bcl);
  k_dotzero<<<(Bsz * Dd + 255) / 256, 256, 0, st2>>>(x, wq_out, S, gx);

  // ---- backward init (layer 9) -> ga9 in zh2[0], Acat buf[1] ----
  k_bwinit<<<(Bsz * Hh + 255) / 256, 256>>>(F, U, wz_out, zh2[0], zl2[0],
                                            Ach[1], Acl[1]);
  cudaEventRecord(evBw[9], 0);

  cudaStreamWaitEvent(st2, evBw[9], 0);
  {
    EpiP ep = {};
    ep.gx = gx;
    mma_gemm<4><<<dim3(1, Bsz / 128, 2), 256, SMEM_SZ, st2>>>(
        Ach[1], Acl[1], Bch + (size_t)(Ll - 1) * Dd * 1024,
        Bcl + (size_t)(Ll - 1) * Dd * 1024, 512, 1024, 1024, ep);
    cudaEventRecord(evTail[9], st2);
  }

  // ---- backward chain on s0, tails on s2 ----
  cudaStreamWaitEvent(0, evWzT, 0);
  int cur = 0;
  for (int l = Ll - 2; l >= 0; --l) {
    if (l + 2 <= 9) cudaStreamWaitEvent(0, evTail[l + 2], 0);
    {
      EpiP ep = {};
      ep.F = F;
      ep.U = U;
      ep.coff = l * Hh;
      ep.zh = zh2[cur ^ 1];
      ep.zl = zl2[cur ^ 1];
      ep.ach = Ach[l & 1];
      ep.acl = Acl[l & 1];
      mma_gemm<3><<<dim3(Hh / 128, Bsz / 128, 1), 256, SMEM_SZ>>>(
          zh2[cur], zl2[cur], WzTh + (size_t)l * Hh * Hh,
          WzTl + (size_t)l * Hh * Hh, Hh, Hh, Hh, ep);
      cur ^= 1;
    }
    cudaEventRecord(evBw[l], 0);
    cudaStreamWaitEvent(st2, evBw[l], 0);
    {
      EpiP ep = {};
      ep.gx = gx;
      mma_gemm<4><<<dim3(1, Bsz / 128, 2), 256, SMEM_SZ, st2>>>(
          Ach[l & 1], Acl[l & 1], Bch + (size_t)l * Dd * 1024,
          Bcl + (size_t)l * Dd * 1024, 512, 1024, 1024, ep);
      cudaEventRecord(evTail[l], st2);
    }
  }

  // ---- join and final combine ----
  cudaStreamWaitEvent(0, evTail[0], 0);
  k_final<<<(Bsz * Dd + 255) / 256, 256>>>(gx, S, wq_out, wl_out, x, out);
}